// round 2
// baseline (speedup 1.0000x reference)
#include <cuda_runtime.h>

#define BB 128
#define SS 4096
#define CC 64
#define TILE 256
#define NW 8
#define THREADS (NW * 32)
#define PSTRIDE (TILE + 1)   // 257 floats per c-row of transposed p

// packed f32x2 FMA (Blackwell): d = a*b + c elementwise on a 64-bit pair
__device__ __forceinline__ float2 ffma2(float2 a, float2 b, float2 c) {
    float2 d;
    asm("{\n\t"
        ".reg .b64 ra, rb, rc, rd;\n\t"
        "mov.b64 ra, {%2, %3};\n\t"
        "mov.b64 rb, {%4, %5};\n\t"
        "mov.b64 rc, {%6, %7};\n\t"
        "fma.rn.f32x2 rd, ra, rb, rc;\n\t"
        "mov.b64 {%0, %1}, rd;\n\t"
        "}"
        : "=f"(d.x), "=f"(d.y)
        : "f"(a.x), "f"(a.y), "f"(b.x), "f"(b.y), "f"(c.x), "f"(c.y));
    return d;
}

__global__ __launch_bounds__(THREADS) void pk_kernel(
    const float* __restrict__ logits,
    const float* __restrict__ M,
    float* __restrict__ out)
{
    extern __shared__ float dsm[];
    float* spT = dsm;                                  // [CC][PSTRIDE]
    float4* sM4 = (float4*)(dsm + CC * PSTRIDE);       // [CC][16] (row-major M as float4)

    const int b    = blockIdx.y;
    const int t0   = blockIdx.x * TILE;
    const int tid  = threadIdx.x;
    const int w    = tid >> 5;
    const int lane = tid & 31;

    const int ntok = min(TILE + 1, SS - t0);   // p rows needed
    const int nout = min(TILE, SS - 1 - t0);   // outputs produced

    // ---- stage M into smem ----
    {
        const float4* M4 = (const float4*)M;
        #pragma unroll 4
        for (int i = tid; i < CC * CC / 4; i += THREADS)
            sM4[i] = M4[i];
    }

    // ---- phase 1: log-softmax, one warp per token, store TRANSPOSED ----
    const float* lg = logits + ((size_t)b * SS + t0) * CC;
    for (int t = w; t < ntok; t += NW) {
        float x0 = lg[t * CC + lane];
        float x1 = lg[t * CC + lane + 32];
        float m = fmaxf(x0, x1);
        #pragma unroll
        for (int o = 16; o; o >>= 1) m = fmaxf(m, __shfl_xor_sync(0xffffffffu, m, o));
        float s = __expf(x0 - m) + __expf(x1 - m);
        #pragma unroll
        for (int o = 16; o; o >>= 1) s += __shfl_xor_sync(0xffffffffu, s, o);
        float lse = m + __logf(s);
        spT[lane * PSTRIDE + t]        = x0 - lse;   // banks (lane+t)%32 -> conflict-free
        spT[(lane + 32) * PSTRIDE + t] = x1 - lse;
    }
    __syncthreads();

    // ---- phase 2: lane owns token i; q = M^T p_i accumulated in regs ----
    const int i = w * 32 + lane;          // token index within tile, 0..TILE-1

    float2 acc[CC / 2];
    #pragma unroll
    for (int d = 0; d < CC / 2; d++) acc[d] = make_float2(0.f, 0.f);

    #pragma unroll 4
    for (int c = 0; c < CC; c++) {
        float pc = spT[c * PSTRIDE + i];          // coalesced, conflict-free
        const float4* mr = sM4 + c * (CC / 4);    // broadcast loads
        #pragma unroll
        for (int k = 0; k < CC / 4; k++) {
            float4 m4 = mr[k];
            acc[2 * k]     = ffma2(make_float2(pc, pc), make_float2(m4.x, m4.y), acc[2 * k]);
            acc[2 * k + 1] = ffma2(make_float2(pc, pc), make_float2(m4.z, m4.w), acc[2 * k + 1]);
        }
    }

    // ---- epilogue: v = q . p_{i+1}, per-lane scalar, coalesced store ----
    float v = 0.f;
    const int ii = i + 1;
    #pragma unroll
    for (int d = 0; d < CC / 2; d++) {
        float a0 = spT[(2 * d) * PSTRIDE + ii];
        float a1 = spT[(2 * d + 1) * PSTRIDE + ii];
        v = fmaf(acc[d].x, a0, v);
        v = fmaf(acc[d].y, a1, v);
    }

    if (i < nout)
        out[(size_t)b * (SS - 1) + t0 + i] = v;
}

extern "C" void kernel_launch(void* const* d_in, const int* in_sizes, int n_in,
                              void* d_out, int out_size)
{
    const float* logits = (const float*)d_in[0];
    const float* M      = (const float*)d_in[1];
    float* out          = (float*)d_out;

    size_t smem = (size_t)CC * PSTRIDE * sizeof(float) + (size_t)CC * CC * sizeof(float);
    cudaFuncSetAttribute(pk_kernel, cudaFuncAttributeMaxDynamicSharedMemorySize, (int)smem);

    dim3 grid(SS / TILE, BB);
    pk_kernel<<<grid, THREADS, smem>>>(logits, M, out);
}

// round 5
// speedup vs baseline: 1.1729x; 1.1729x over previous
#include <cuda_runtime.h>
#include <cuda_bf16.h>
#include <cstdint>

#define BB 128
#define SS 4096
#define CC 64
#define TILE 128
#define NW 8
#define THREADS (NW * 32)

#define SA 66            // bf16 stride for A tiles (132B rows)
#define SB 66            // bf16 stride for B tiles
#define OFF_AHI 0
#define OFF_ALO 17040    // 129*66*2 = 17028 -> pad 17040
#define OFF_BHI 34080
#define OFF_BLO 42528    // + 64*66*2 = 8448
#define SMEM_TOTAL 50976

#define MMA16816(d0,d1,d2,d3,a,b0,b1)                                        \
    asm volatile("mma.sync.aligned.m16n8k16.row.col.f32.bf16.bf16.f32 "      \
        "{%0,%1,%2,%3}, {%4,%5,%6,%7}, {%8,%9}, {%0,%1,%2,%3};"              \
        : "+f"(d0), "+f"(d1), "+f"(d2), "+f"(d3)                              \
        : "r"((a)[0]), "r"((a)[1]), "r"((a)[2]), "r"((a)[3]), "r"(b0), "r"(b1))

__global__ __launch_bounds__(THREADS) void pk_kernel(
    const float* __restrict__ logits,
    const float* __restrict__ M,
    float* __restrict__ out)
{
    extern __shared__ char dsm[];
    __nv_bfloat16* Ahi = (__nv_bfloat16*)(dsm + OFF_AHI);   // [129][SA] p hi
    __nv_bfloat16* Alo = (__nv_bfloat16*)(dsm + OFF_ALO);   // [129][SA] p lo
    __nv_bfloat16* Bhi = (__nv_bfloat16*)(dsm + OFF_BHI);   // [64][SB]  M^T hi (col-major M)
    __nv_bfloat16* Blo = (__nv_bfloat16*)(dsm + OFF_BLO);   // [64][SB]  M^T lo

    const int b    = blockIdx.y;
    const int t0   = blockIdx.x * TILE;
    const int tid  = threadIdx.x;
    const int w    = tid >> 5;
    const int lane = tid & 31;

    const int ntok = min(TILE + 1, SS - t0);   // p rows to build (129, or 128 last tile)
    const int nout = min(TILE, SS - 1 - t0);   // outputs (128, or 127 last tile)

    // ---- stage B = M^T as bf16 hi/lo (coalesced gmem reads) ----
    for (int idx = tid; idx < CC * CC; idx += THREADS) {
        int k = idx >> 6, n = idx & 63;
        float v = M[idx];                       // M[k][n]
        __nv_bfloat16 h = __float2bfloat16(v);
        __nv_bfloat16 l = __float2bfloat16(v - __bfloat162float(h));
        Bhi[n * SB + k] = h;
        Blo[n * SB + k] = l;
    }

    // ---- phase 1: log-softmax, warp-per-token, bf16 hi/lo to smem ----
    const float* lg = logits + ((size_t)b * SS + t0) * CC;
    for (int t = w; t < ntok; t += NW) {
        float x0 = lg[t * CC + lane];
        float x1 = lg[t * CC + lane + 32];
        float m = fmaxf(x0, x1);
        #pragma unroll
        for (int o = 16; o; o >>= 1) m = fmaxf(m, __shfl_xor_sync(0xffffffffu, m, o));
        float s = __expf(x0 - m) + __expf(x1 - m);
        #pragma unroll
        for (int o = 16; o; o >>= 1) s += __shfl_xor_sync(0xffffffffu, s, o);
        float lse = m + __logf(s);
        float p0 = x0 - lse, p1 = x1 - lse;

        __nv_bfloat16 h0 = __float2bfloat16(p0);
        __nv_bfloat16 h1 = __float2bfloat16(p1);
        Ahi[t * SA + lane]      = h0;
        Ahi[t * SA + lane + 32] = h1;
        Alo[t * SA + lane]      = __float2bfloat16(p0 - __bfloat162float(h0));
        Alo[t * SA + lane + 32] = __float2bfloat16(p1 - __bfloat162float(h1));
    }
    __syncthreads();

    // ---- phase 2: warp w owns token rows [16w, 16w+16) ----
    const int g  = lane >> 2;     // 0..7
    const int t4 = lane & 3;      // 0..3
    const int rb = w * 16;

    // cache A fragments for all 4 k-chunks, both terms (32 regs)
    uint32_t ahi[4][4], alo[4][4];
    #pragma unroll
    for (int kc = 0; kc < 4; kc++) {
        int kb = kc * 16 + 2 * t4;
        ahi[kc][0] = *(const uint32_t*)&Ahi[(rb + g)     * SA + kb];
        ahi[kc][1] = *(const uint32_t*)&Ahi[(rb + g + 8) * SA + kb];
        ahi[kc][2] = *(const uint32_t*)&Ahi[(rb + g)     * SA + kb + 8];
        ahi[kc][3] = *(const uint32_t*)&Ahi[(rb + g + 8) * SA + kb + 8];
        alo[kc][0] = *(const uint32_t*)&Alo[(rb + g)     * SA + kb];
        alo[kc][1] = *(const uint32_t*)&Alo[(rb + g + 8) * SA + kb];
        alo[kc][2] = *(const uint32_t*)&Alo[(rb + g)     * SA + kb + 8];
        alo[kc][3] = *(const uint32_t*)&Alo[(rb + g + 8) * SA + kb + 8];
    }

    float v0 = 0.f, v1 = 0.f;

    #pragma unroll
    for (int nc = 0; nc < 8; nc++) {
        const int nb = nc * 8;
        float d0 = 0.f, d1 = 0.f, d2 = 0.f, d3 = 0.f;

        #pragma unroll
        for (int kc = 0; kc < 4; kc++) {
            int kb = kc * 16 + 2 * t4;
            uint32_t bh0 = *(const uint32_t*)&Bhi[(nb + g) * SB + kb];
            uint32_t bh1 = *(const uint32_t*)&Bhi[(nb + g) * SB + kb + 8];
            uint32_t bl0 = *(const uint32_t*)&Blo[(nb + g) * SB + kb];
            uint32_t bl1 = *(const uint32_t*)&Blo[(nb + g) * SB + kb + 8];
            MMA16816(d0, d1, d2, d3, ahi[kc], bh0, bh1);   // Ahi*Bhi
            MMA16816(d0, d1, d2, d3, ahi[kc], bl0, bl1);   // Ahi*Blo
            MMA16816(d0, d1, d2, d3, alo[kc], bh0, bh1);   // Alo*Bhi
        }

        // epilogue for this n-chunk: dot with p_{i+1}[nb+2t4, nb+2t4+1]
        const int c0 = nb + 2 * t4;
        uint32_t phA = *(const uint32_t*)&Ahi[(rb + g + 1) * SA + c0];
        uint32_t plA = *(const uint32_t*)&Alo[(rb + g + 1) * SA + c0];
        uint32_t phB = *(const uint32_t*)&Ahi[(rb + g + 9) * SA + c0];
        uint32_t plB = *(const uint32_t*)&Alo[(rb + g + 9) * SA + c0];
        __nv_bfloat162 hA = *(__nv_bfloat162*)&phA, lA = *(__nv_bfloat162*)&plA;
        __nv_bfloat162 hB = *(__nv_bfloat162*)&phB, lB = *(__nv_bfloat162*)&plB;
        float pxA = __low2float(hA)  + __low2float(lA);
        float pyA = __high2float(hA) + __high2float(lA);
        float pxB = __low2float(hB)  + __low2float(lB);
        float pyB = __high2float(hB) + __high2float(lB);

        v0 = fmaf(d0, pxA, v0); v0 = fmaf(d1, pyA, v0);
        v1 = fmaf(d2, pxB, v1); v1 = fmaf(d3, pyB, v1);
    }

    // reduce over the 4-lane quad (t4)
    v0 += __shfl_xor_sync(0xffffffffu, v0, 1);
    v0 += __shfl_xor_sync(0xffffffffu, v0, 2);
    v1 += __shfl_xor_sync(0xffffffffu, v1, 1);
    v1 += __shfl_xor_sync(0xffffffffu, v1, 2);

    if (t4 == 0) {
        float* outp = out + (size_t)b * (SS - 1) + t0;
        int i0 = rb + g, i1 = rb + g + 8;
        if (i0 < nout) outp[i0] = v0;
        if (i1 < nout) outp[i1] = v1;
    }
}

extern "C" void kernel_launch(void* const* d_in, const int* in_sizes, int n_in,
                              void* d_out, int out_size)
{
    const float* logits = (const float*)d_in[0];
    const float* M      = (const float*)d_in[1];
    float* out          = (float*)d_out;

    cudaFuncSetAttribute(pk_kernel, cudaFuncAttributeMaxDynamicSharedMemorySize, SMEM_TOTAL);
    dim3 grid(SS / TILE, BB);
    pk_kernel<<<grid, THREADS, SMEM_TOTAL>>>(logits, M, out);
}

// round 6
// speedup vs baseline: 1.2575x; 1.0721x over previous
#include <cuda_runtime.h>
#include <cuda_bf16.h>
#include <cstdint>

#define BB 128
#define SS 4096
#define CC 64
#define TILE 128
#define NW 8
#define THREADS (NW * 32)

#define SA 66            // bf16 stride for A tiles (132B rows)
#define SB 66            // bf16 stride for B tiles
#define OFF_AHI 0
#define OFF_ALO 17040    // 129*66*2 = 17028 -> pad 17040
#define OFF_BHI 34080
#define OFF_BLO 42528
#define SMEM_TOTAL 50976

#define MMA16816(d0,d1,d2,d3,a,b0,b1)                                        \
    asm volatile("mma.sync.aligned.m16n8k16.row.col.f32.bf16.bf16.f32 "      \
        "{%0,%1,%2,%3}, {%4,%5,%6,%7}, {%8,%9}, {%0,%1,%2,%3};"              \
        : "+f"(d0), "+f"(d1), "+f"(d2), "+f"(d3)                              \
        : "r"((a)[0]), "r"((a)[1]), "r"((a)[2]), "r"((a)[3]), "r"(b0), "r"(b1))

// ---- packed f32x2 ops (Blackwell) ----
__device__ __forceinline__ float2 ffma2(float2 a, float2 b, float2 c) {
    float2 d;
    asm("{ .reg .b64 ra, rb, rc, rd;\n\t"
        "mov.b64 ra, {%2, %3}; mov.b64 rb, {%4, %5}; mov.b64 rc, {%6, %7};\n\t"
        "fma.rn.f32x2 rd, ra, rb, rc;\n\t"
        "mov.b64 {%0, %1}, rd; }"
        : "=f"(d.x), "=f"(d.y)
        : "f"(a.x), "f"(a.y), "f"(b.x), "f"(b.y), "f"(c.x), "f"(c.y));
    return d;
}
__device__ __forceinline__ float2 fmul2(float2 a, float2 b) {
    float2 d;
    asm("{ .reg .b64 ra, rb, rd;\n\t"
        "mov.b64 ra, {%2, %3}; mov.b64 rb, {%4, %5};\n\t"
        "mul.rn.f32x2 rd, ra, rb;\n\t"
        "mov.b64 {%0, %1}, rd; }"
        : "=f"(d.x), "=f"(d.y)
        : "f"(a.x), "f"(a.y), "f"(b.x), "f"(b.y));
    return d;
}

// paired exp(x) on the FMA/ALU pipes (no MUFU). |x| < ~80 assumed.
__device__ __forceinline__ float2 fast_exp2x(float2 x) {
    const float L2E   = 1.4426950408889634f;
    const float MAGIC = 12582912.0f;               // 1.5 * 2^23
    float2 y = fmul2(x, make_float2(L2E, L2E));
    float2 t = ffma2(y, make_float2(1.f, 1.f), make_float2(MAGIC, MAGIC)); // y + MAGIC
    float2 n = ffma2(t, make_float2(1.f, 1.f), make_float2(-MAGIC, -MAGIC)); // t - MAGIC
    float2 f = ffma2(n, make_float2(-1.f, -1.f), y);                          // y - n
    // 2^f, f in [-0.5, 0.5]
    float2 p = make_float2(1.3333558146428443e-3f, 1.3333558146428443e-3f);
    p = ffma2(p, f, make_float2(9.6181291076284772e-3f, 9.6181291076284772e-3f));
    p = ffma2(p, f, make_float2(5.5504108664798463e-2f, 5.5504108664798463e-2f));
    p = ffma2(p, f, make_float2(2.4022650695910072e-1f, 2.4022650695910072e-1f));
    p = ffma2(p, f, make_float2(6.9314718055994531e-1f, 6.9314718055994531e-1f));
    p = ffma2(p, f, make_float2(1.0f, 1.0f));
    float2 sc;
    sc.x = __int_as_float((__float_as_int(t.x) - 0x4B400000 + 127) << 23);
    sc.y = __int_as_float((__float_as_int(t.y) - 0x4B400000 + 127) << 23);
    return fmul2(p, sc);
}

__global__ __launch_bounds__(THREADS) void pk_kernel(
    const float* __restrict__ logits,
    const float* __restrict__ M,
    float* __restrict__ out)
{
    extern __shared__ char dsm[];
    __nv_bfloat16* Ahi = (__nv_bfloat16*)(dsm + OFF_AHI);
    __nv_bfloat16* Alo = (__nv_bfloat16*)(dsm + OFF_ALO);
    __nv_bfloat16* Bhi = (__nv_bfloat16*)(dsm + OFF_BHI);
    __nv_bfloat16* Blo = (__nv_bfloat16*)(dsm + OFF_BLO);

    const int b    = blockIdx.y;
    const int t0   = blockIdx.x * TILE;
    const int tid  = threadIdx.x;
    const int w    = tid >> 5;
    const int lane = tid & 31;

    const int ntok = min(TILE + 1, SS - t0);
    const int nout = min(TILE, SS - 1 - t0);

    // ---- stage B = M^T as bf16 hi/lo ----
    for (int idx = tid; idx < CC * CC; idx += THREADS) {
        int k = idx >> 6, n = idx & 63;
        float v = M[idx];
        __nv_bfloat16 h = __float2bfloat16(v);
        __nv_bfloat16 l = __float2bfloat16(v - __bfloat162float(h));
        Bhi[n * SB + k] = h;
        Blo[n * SB + k] = l;
    }

    // ---- phase 1: log-softmax (no max-subtract; poly exp on FMA pipe) ----
    const float* lg = logits + ((size_t)b * SS + t0) * CC;
    for (int t = w; t < ntok; t += NW) {
        float x0 = lg[t * CC + lane];
        float x1 = lg[t * CC + lane + 32];

        float2 e = fast_exp2x(make_float2(x0, x1));
        float s = e.x + e.y;
        #pragma unroll
        for (int o = 16; o; o >>= 1) s += __shfl_xor_sync(0xffffffffu, s, o);
        float lse = __logf(s);
        float p0 = x0 - lse, p1 = x1 - lse;

        __nv_bfloat16 h0 = __float2bfloat16(p0);
        __nv_bfloat16 h1 = __float2bfloat16(p1);
        Ahi[t * SA + lane]      = h0;
        Ahi[t * SA + lane + 32] = h1;
        Alo[t * SA + lane]      = __float2bfloat16(p0 - __bfloat162float(h0));
        Alo[t * SA + lane + 32] = __float2bfloat16(p1 - __bfloat162float(h1));
    }
    __syncthreads();

    // ---- phase 2: warp w owns token rows [16w, 16w+16) ----
    const int g  = lane >> 2;
    const int t4 = lane & 3;
    const int rb = w * 16;

    uint32_t ahi[4][4], alo[4][4];
    #pragma unroll
    for (int kc = 0; kc < 4; kc++) {
        int kb = kc * 16 + 2 * t4;
        ahi[kc][0] = *(const uint32_t*)&Ahi[(rb + g)     * SA + kb];
        ahi[kc][1] = *(const uint32_t*)&Ahi[(rb + g + 8) * SA + kb];
        ahi[kc][2] = *(const uint32_t*)&Ahi[(rb + g)     * SA + kb + 8];
        ahi[kc][3] = *(const uint32_t*)&Ahi[(rb + g + 8) * SA + kb + 8];
        alo[kc][0] = *(const uint32_t*)&Alo[(rb + g)     * SA + kb];
        alo[kc][1] = *(const uint32_t*)&Alo[(rb + g + 8) * SA + kb];
        alo[kc][2] = *(const uint32_t*)&Alo[(rb + g)     * SA + kb + 8];
        alo[kc][3] = *(const uint32_t*)&Alo[(rb + g + 8) * SA + kb + 8];
    }

    float v0 = 0.f, v1 = 0.f;

    #pragma unroll
    for (int nc = 0; nc < 8; nc++) {
        const int nb = nc * 8;
        float d0 = 0.f, d1 = 0.f, d2 = 0.f, d3 = 0.f;

        #pragma unroll
        for (int kc = 0; kc < 4; kc++) {
            int kb = kc * 16 + 2 * t4;
            uint32_t bh0 = *(const uint32_t*)&Bhi[(nb + g) * SB + kb];
            uint32_t bh1 = *(const uint32_t*)&Bhi[(nb + g) * SB + kb + 8];
            uint32_t bl0 = *(const uint32_t*)&Blo[(nb + g) * SB + kb];
            uint32_t bl1 = *(const uint32_t*)&Blo[(nb + g) * SB + kb + 8];
            MMA16816(d0, d1, d2, d3, ahi[kc], bh0, bh1);
            MMA16816(d0, d1, d2, d3, ahi[kc], bl0, bl1);
            MMA16816(d0, d1, d2, d3, alo[kc], bh0, bh1);
        }

        const int c0 = nb + 2 * t4;
        uint32_t phA = *(const uint32_t*)&Ahi[(rb + g + 1) * SA + c0];
        uint32_t plA = *(const uint32_t*)&Alo[(rb + g + 1) * SA + c0];
        uint32_t phB = *(const uint32_t*)&Ahi[(rb + g + 9) * SA + c0];
        uint32_t plB = *(const uint32_t*)&Alo[(rb + g + 9) * SA + c0];
        __nv_bfloat162 hA = *(__nv_bfloat162*)&phA, lA = *(__nv_bfloat162*)&plA;
        __nv_bfloat162 hB = *(__nv_bfloat162*)&phB, lB = *(__nv_bfloat162*)&plB;
        float pxA = __low2float(hA)  + __low2float(lA);
        float pyA = __high2float(hA) + __high2float(lA);
        float pxB = __low2float(hB)  + __low2float(lB);
        float pyB = __high2float(hB) + __high2float(lB);

        v0 = fmaf(d0, pxA, v0); v0 = fmaf(d1, pyA, v0);
        v1 = fmaf(d2, pxB, v1); v1 = fmaf(d3, pyB, v1);
    }

    v0 += __shfl_xor_sync(0xffffffffu, v0, 1);
    v0 += __shfl_xor_sync(0xffffffffu, v0, 2);
    v1 += __shfl_xor_sync(0xffffffffu, v1, 1);
    v1 += __shfl_xor_sync(0xffffffffu, v1, 2);

    if (t4 == 0) {
        float* outp = out + (size_t)b * (SS - 1) + t0;
        int i0 = rb + g, i1 = rb + g + 8;
        if (i0 < nout) outp[i0] = v0;
        if (i1 < nout) outp[i1] = v1;
    }
}

extern "C" void kernel_launch(void* const* d_in, const int* in_sizes, int n_in,
                              void* d_out, int out_size)
{
    const float* logits = (const float*)d_in[0];
    const float* M      = (const float*)d_in[1];
    float* out          = (float*)d_out;

    cudaFuncSetAttribute(pk_kernel, cudaFuncAttributeMaxDynamicSharedMemorySize, SMEM_TOTAL);
    dim3 grid(SS / TILE, BB);
    pk_kernel<<<grid, THREADS, SMEM_TOTAL>>>(logits, M, out);
}

// round 7
// speedup vs baseline: 1.5593x; 1.2400x over previous
#include <cuda_runtime.h>
#include <cuda_bf16.h>
#include <cstdint>

#define BB 128
#define SS 4096
#define CC 64
#define TILE 128
#define NW 8
#define THREADS (NW * 32)

#define SA 66            // bf16 stride for A tiles
#define SB 66
#define OFF_LG  0                        // [129][64] f32 staged logits = 33024 B
#define OFF_AHI 33024
#define OFF_ALO (OFF_AHI + 17040)        // 129*66*2 = 17028 -> 17040
#define OFF_BHI (OFF_ALO + 17040)
#define OFF_BLO (OFF_BHI + 8448)         // 64*66*2 = 8448
#define SMEM_TOTAL (OFF_BLO + 8448)      // 84000

#define MMA16816(d0,d1,d2,d3,a,b0,b1)                                        \
    asm volatile("mma.sync.aligned.m16n8k16.row.col.f32.bf16.bf16.f32 "      \
        "{%0,%1,%2,%3}, {%4,%5,%6,%7}, {%8,%9}, {%0,%1,%2,%3};"              \
        : "+f"(d0), "+f"(d1), "+f"(d2), "+f"(d3)                              \
        : "r"((a)[0]), "r"((a)[1]), "r"((a)[2]), "r"((a)[3]), "r"(b0), "r"(b1))

static __device__ __forceinline__ uint32_t smem_u32(const void* p) {
    uint32_t a;
    asm("{ .reg .u64 t; cvta.to.shared.u64 t, %1; cvt.u32.u64 %0, t; }" : "=r"(a) : "l"(p));
    return a;
}

// ---- packed f32x2 ops ----
__device__ __forceinline__ float2 ffma2(float2 a, float2 b, float2 c) {
    float2 d;
    asm("{ .reg .b64 ra, rb, rc, rd;\n\t"
        "mov.b64 ra, {%2, %3}; mov.b64 rb, {%4, %5}; mov.b64 rc, {%6, %7};\n\t"
        "fma.rn.f32x2 rd, ra, rb, rc;\n\t"
        "mov.b64 {%0, %1}, rd; }"
        : "=f"(d.x), "=f"(d.y)
        : "f"(a.x), "f"(a.y), "f"(b.x), "f"(b.y), "f"(c.x), "f"(c.y));
    return d;
}
__device__ __forceinline__ float2 fmul2(float2 a, float2 b) {
    float2 d;
    asm("{ .reg .b64 ra, rb, rd;\n\t"
        "mov.b64 ra, {%2, %3}; mov.b64 rb, {%4, %5};\n\t"
        "mul.rn.f32x2 rd, ra, rb;\n\t"
        "mov.b64 {%0, %1}, rd; }"
        : "=f"(d.x), "=f"(d.y)
        : "f"(a.x), "f"(a.y), "f"(b.x), "f"(b.y));
    return d;
}

// paired exp(x) on FMA/ALU pipes (no MUFU)
__device__ __forceinline__ float2 fast_exp2x(float2 x) {
    const float L2E   = 1.4426950408889634f;
    const float MAGIC = 12582912.0f;               // 1.5 * 2^23
    float2 y = fmul2(x, make_float2(L2E, L2E));
    float2 t = ffma2(y, make_float2(1.f, 1.f), make_float2(MAGIC, MAGIC));
    float2 n = ffma2(t, make_float2(1.f, 1.f), make_float2(-MAGIC, -MAGIC));
    float2 f = ffma2(n, make_float2(-1.f, -1.f), y);
    float2 p = make_float2(1.3333558146428443e-3f, 1.3333558146428443e-3f);
    p = ffma2(p, f, make_float2(9.6181291076284772e-3f, 9.6181291076284772e-3f));
    p = ffma2(p, f, make_float2(5.5504108664798463e-2f, 5.5504108664798463e-2f));
    p = ffma2(p, f, make_float2(2.4022650695910072e-1f, 2.4022650695910072e-1f));
    p = ffma2(p, f, make_float2(6.9314718055994531e-1f, 6.9314718055994531e-1f));
    p = ffma2(p, f, make_float2(1.0f, 1.0f));
    float2 sc;
    sc.x = __int_as_float((__float_as_int(t.x) - 0x4B400000 + 127) << 23);
    sc.y = __int_as_float((__float_as_int(t.y) - 0x4B400000 + 127) << 23);
    return fmul2(p, sc);
}

__global__ __launch_bounds__(THREADS) void pk_kernel(
    const float* __restrict__ logits,
    const float* __restrict__ M,
    float* __restrict__ out)
{
    extern __shared__ char dsm[];
    float*         sLg = (float*)(dsm + OFF_LG);             // [129][64]
    __nv_bfloat16* Ahi = (__nv_bfloat16*)(dsm + OFF_AHI);
    __nv_bfloat16* Alo = (__nv_bfloat16*)(dsm + OFF_ALO);
    __nv_bfloat16* Bhi = (__nv_bfloat16*)(dsm + OFF_BHI);
    __nv_bfloat16* Blo = (__nv_bfloat16*)(dsm + OFF_BLO);

    const int b    = blockIdx.y;
    const int t0   = blockIdx.x * TILE;
    const int tid  = threadIdx.x;
    const int w    = tid >> 5;
    const int lane = tid & 31;

    const int ntok = min(TILE + 1, SS - t0);
    const int nout = min(TILE, SS - 1 - t0);

    // ---- phase 0: bulk cp.async of the whole logits tile (massive MLP) ----
    {
        const uint32_t sLg32 = smem_u32(sLg);
        const float4* src = (const float4*)(logits + ((size_t)b * SS + t0) * CC);
        const int total4 = ntok * (CC / 4);      // 16 float4 per token row
        #pragma unroll 4
        for (int i = tid; i < total4; i += THREADS) {
            asm volatile("cp.async.cg.shared.global [%0], [%1], 16;"
                         :: "r"(sLg32 + i * 16), "l"(src + i) : "memory");
        }
        asm volatile("cp.async.commit_group;" ::: "memory");
    }

    // ---- stage B = M^T as bf16 hi/lo (overlaps with cp.async flight) ----
    for (int idx = tid; idx < CC * CC; idx += THREADS) {
        int k = idx >> 6, n = idx & 63;
        float v = M[idx];
        __nv_bfloat16 h = __float2bfloat16(v);
        __nv_bfloat16 l = __float2bfloat16(v - __bfloat162float(h));
        Bhi[n * SB + k] = h;
        Blo[n * SB + k] = l;
    }

    asm volatile("cp.async.wait_group 0;" ::: "memory");
    __syncthreads();

    // ---- phase 1: log-softmax from smem, warp-per-token ----
    for (int t = w; t < ntok; t += NW) {
        float x0 = sLg[t * CC + lane];
        float x1 = sLg[t * CC + lane + 32];

        float2 e = fast_exp2x(make_float2(x0, x1));
        float s = e.x + e.y;
        #pragma unroll
        for (int o = 16; o; o >>= 1) s += __shfl_xor_sync(0xffffffffu, s, o);
        float lse = __logf(s);
        float p0 = x0 - lse, p1 = x1 - lse;

        __nv_bfloat16 h0 = __float2bfloat16(p0);
        __nv_bfloat16 h1 = __float2bfloat16(p1);
        Ahi[t * SA + lane]      = h0;
        Ahi[t * SA + lane + 32] = h1;
        Alo[t * SA + lane]      = __float2bfloat16(p0 - __bfloat162float(h0));
        Alo[t * SA + lane + 32] = __float2bfloat16(p1 - __bfloat162float(h1));
    }
    __syncthreads();

    // ---- phase 2: warp w owns token rows [16w, 16w+16) ----
    const int g  = lane >> 2;
    const int t4 = lane & 3;
    const int rb = w * 16;

    uint32_t ahi[4][4], alo[4][4];
    #pragma unroll
    for (int kc = 0; kc < 4; kc++) {
        int kb = kc * 16 + 2 * t4;
        ahi[kc][0] = *(const uint32_t*)&Ahi[(rb + g)     * SA + kb];
        ahi[kc][1] = *(const uint32_t*)&Ahi[(rb + g + 8) * SA + kb];
        ahi[kc][2] = *(const uint32_t*)&Ahi[(rb + g)     * SA + kb + 8];
        ahi[kc][3] = *(const uint32_t*)&Ahi[(rb + g + 8) * SA + kb + 8];
        alo[kc][0] = *(const uint32_t*)&Alo[(rb + g)     * SA + kb];
        alo[kc][1] = *(const uint32_t*)&Alo[(rb + g + 8) * SA + kb];
        alo[kc][2] = *(const uint32_t*)&Alo[(rb + g)     * SA + kb + 8];
        alo[kc][3] = *(const uint32_t*)&Alo[(rb + g + 8) * SA + kb + 8];
    }

    float v0 = 0.f, v1 = 0.f;

    #pragma unroll
    for (int nc = 0; nc < 8; nc++) {
        const int nb = nc * 8;
        float d0 = 0.f, d1 = 0.f, d2 = 0.f, d3 = 0.f;

        #pragma unroll
        for (int kc = 0; kc < 4; kc++) {
            int kb = kc * 16 + 2 * t4;
            uint32_t bh0 = *(const uint32_t*)&Bhi[(nb + g) * SB + kb];
            uint32_t bh1 = *(const uint32_t*)&Bhi[(nb + g) * SB + kb + 8];
            uint32_t bl0 = *(const uint32_t*)&Blo[(nb + g) * SB + kb];
            uint32_t bl1 = *(const uint32_t*)&Blo[(nb + g) * SB + kb + 8];
            MMA16816(d0, d1, d2, d3, ahi[kc], bh0, bh1);
            MMA16816(d0, d1, d2, d3, ahi[kc], bl0, bl1);
            MMA16816(d0, d1, d2, d3, alo[kc], bh0, bh1);
        }

        const int c0 = nb + 2 * t4;
        uint32_t phA = *(const uint32_t*)&Ahi[(rb + g + 1) * SA + c0];
        uint32_t plA = *(const uint32_t*)&Alo[(rb + g + 1) * SA + c0];
        uint32_t phB = *(const uint32_t*)&Ahi[(rb + g + 9) * SA + c0];
        uint32_t plB = *(const uint32_t*)&Alo[(rb + g + 9) * SA + c0];
        __nv_bfloat162 hA = *(__nv_bfloat162*)&phA, lA = *(__nv_bfloat162*)&plA;
        __nv_bfloat162 hB = *(__nv_bfloat162*)&phB, lB = *(__nv_bfloat162*)&plB;
        float pxA = __low2float(hA)  + __low2float(lA);
        float pyA = __high2float(hA) + __high2float(lA);
        float pxB = __low2float(hB)  + __low2float(lB);
        float pyB = __high2float(hB) + __high2float(lB);

        v0 = fmaf(d0, pxA, v0); v0 = fmaf(d1, pyA, v0);
        v1 = fmaf(d2, pxB, v1); v1 = fmaf(d3, pyB, v1);
    }

    v0 += __shfl_xor_sync(0xffffffffu, v0, 1);
    v0 += __shfl_xor_sync(0xffffffffu, v0, 2);
    v1 += __shfl_xor_sync(0xffffffffu, v1, 1);
    v1 += __shfl_xor_sync(0xffffffffu, v1, 2);

    if (t4 == 0) {
        float* outp = out + (size_t)b * (SS - 1) + t0;
        int i0 = rb + g, i1 = rb + g + 8;
        if (i0 < nout) outp[i0] = v0;
        if (i1 < nout) outp[i1] = v1;
    }
}

extern "C" void kernel_launch(void* const* d_in, const int* in_sizes, int n_in,
                              void* d_out, int out_size)
{
    const float* logits = (const float*)d_in[0];
    const float* M      = (const float*)d_in[1];
    float* out          = (float*)d_out;

    cudaFuncSetAttribute(pk_kernel, cudaFuncAttributeMaxDynamicSharedMemorySize, SMEM_TOTAL);
    dim3 grid(SS / TILE, BB);
    pk_kernel<<<grid, THREADS, SMEM_TOTAL>>>(logits, M, out);
}

// round 8
// speedup vs baseline: 1.6478x; 1.0568x over previous
#include <cuda_runtime.h>
#include <cuda_bf16.h>
#include <cstdint>

#define BB 128
#define SS 4096
#define CC 64
#define TILE 128
#define NW 8
#define THREADS (NW * 32)

#define SA 66            // bf16 stride for A tiles
#define SB 66
#define OFF_AHI 0
#define OFF_ALO 17040    // 129*66*2 = 17028 -> pad 17040
#define OFF_BHI 34080
#define OFF_BLO 42528
#define SMEM_TOTAL 50976

#define MMA16816(d0,d1,d2,d3,a,b0,b1)                                        \
    asm volatile("mma.sync.aligned.m16n8k16.row.col.f32.bf16.bf16.f32 "      \
        "{%0,%1,%2,%3}, {%4,%5,%6,%7}, {%8,%9}, {%0,%1,%2,%3};"              \
        : "+f"(d0), "+f"(d1), "+f"(d2), "+f"(d3)                              \
        : "r"((a)[0]), "r"((a)[1]), "r"((a)[2]), "r"((a)[3]), "r"(b0), "r"(b1))

// ---- packed f32x2 ops ----
__device__ __forceinline__ float2 ffma2(float2 a, float2 b, float2 c) {
    float2 d;
    asm("{ .reg .b64 ra, rb, rc, rd;\n\t"
        "mov.b64 ra, {%2, %3}; mov.b64 rb, {%4, %5}; mov.b64 rc, {%6, %7};\n\t"
        "fma.rn.f32x2 rd, ra, rb, rc;\n\t"
        "mov.b64 {%0, %1}, rd; }"
        : "=f"(d.x), "=f"(d.y)
        : "f"(a.x), "f"(a.y), "f"(b.x), "f"(b.y), "f"(c.x), "f"(c.y));
    return d;
}
__device__ __forceinline__ float2 fmul2(float2 a, float2 b) {
    float2 d;
    asm("{ .reg .b64 ra, rb, rd;\n\t"
        "mov.b64 ra, {%2, %3}; mov.b64 rb, {%4, %5};\n\t"
        "mul.rn.f32x2 rd, ra, rb;\n\t"
        "mov.b64 {%0, %1}, rd; }"
        : "=f"(d.x), "=f"(d.y)
        : "f"(a.x), "f"(a.y), "f"(b.x), "f"(b.y));
    return d;
}

// paired exp(x) on FMA/ALU pipes (no MUFU)
__device__ __forceinline__ float2 fast_exp2x(float2 x) {
    const float L2E   = 1.4426950408889634f;
    const float MAGIC = 12582912.0f;               // 1.5 * 2^23
    float2 y = fmul2(x, make_float2(L2E, L2E));
    float2 t = ffma2(y, make_float2(1.f, 1.f), make_float2(MAGIC, MAGIC));
    float2 n = ffma2(t, make_float2(1.f, 1.f), make_float2(-MAGIC, -MAGIC));
    float2 f = ffma2(n, make_float2(-1.f, -1.f), y);
    float2 p = make_float2(1.3333558146428443e-3f, 1.3333558146428443e-3f);
    p = ffma2(p, f, make_float2(9.6181291076284772e-3f, 9.6181291076284772e-3f));
    p = ffma2(p, f, make_float2(5.5504108664798463e-2f, 5.5504108664798463e-2f));
    p = ffma2(p, f, make_float2(2.4022650695910072e-1f, 2.4022650695910072e-1f));
    p = ffma2(p, f, make_float2(6.9314718055994531e-1f, 6.9314718055994531e-1f));
    p = ffma2(p, f, make_float2(1.0f, 1.0f));
    float2 sc;
    sc.x = __int_as_float((__float_as_int(t.x) - 0x4B400000 + 127) << 23);
    sc.y = __int_as_float((__float_as_int(t.y) - 0x4B400000 + 127) << 23);
    return fmul2(p, sc);
}

__global__ __launch_bounds__(THREADS, 3) void pk_kernel(
    const float* __restrict__ logits,
    const float* __restrict__ M,
    float* __restrict__ out)
{
    extern __shared__ char dsm[];
    __nv_bfloat16* Ahi = (__nv_bfloat16*)(dsm + OFF_AHI);
    __nv_bfloat16* Alo = (__nv_bfloat16*)(dsm + OFF_ALO);
    __nv_bfloat16* Bhi = (__nv_bfloat16*)(dsm + OFF_BHI);
    __nv_bfloat16* Blo = (__nv_bfloat16*)(dsm + OFF_BLO);

    const int b    = blockIdx.y;
    const int t0   = blockIdx.x * TILE;
    const int tid  = threadIdx.x;
    const int w    = tid >> 5;
    const int lane = tid & 31;

    const int ntok = min(TILE + 1, SS - t0);
    const int nout = min(TILE, SS - 1 - t0);

    // ---- stage B = M^T as bf16 hi/lo ----
    for (int idx = tid; idx < CC * CC; idx += THREADS) {
        int k = idx >> 6, n = idx & 63;
        float v = M[idx];
        __nv_bfloat16 h = __float2bfloat16(v);
        __nv_bfloat16 l = __float2bfloat16(v - __bfloat162float(h));
        Bhi[n * SB + k] = h;
        Blo[n * SB + k] = l;
    }

    // ---- phase 1: log-softmax, warp-per-token, 4 tokens batched (MLP=8) ----
    const float* lg = logits + ((size_t)b * SS + t0) * CC;
    for (int base = w * 4; base < ntok; base += NW * 4) {
        float x0[4], x1[4];
        #pragma unroll
        for (int j = 0; j < 4; j++) {
            int t = base + j;
            bool ok = (t < ntok);
            int tt = ok ? t : base;
            x0[j] = lg[tt * CC + lane];
            x1[j] = lg[tt * CC + lane + 32];
        }

        float s[4], lse[4];
        #pragma unroll
        for (int j = 0; j < 4; j++) {
            float2 e = fast_exp2x(make_float2(x0[j], x1[j]));
            s[j] = e.x + e.y;
        }
        #pragma unroll
        for (int o = 16; o; o >>= 1) {
            #pragma unroll
            for (int j = 0; j < 4; j++)
                s[j] += __shfl_xor_sync(0xffffffffu, s[j], o);
        }
        #pragma unroll
        for (int j = 0; j < 4; j++) lse[j] = __logf(s[j]);

        #pragma unroll
        for (int j = 0; j < 4; j++) {
            int t = base + j;
            if (t < ntok) {
                float p0 = x0[j] - lse[j], p1 = x1[j] - lse[j];
                __nv_bfloat16 h0 = __float2bfloat16(p0);
                __nv_bfloat16 h1 = __float2bfloat16(p1);
                Ahi[t * SA + lane]      = h0;
                Ahi[t * SA + lane + 32] = h1;
                Alo[t * SA + lane]      = __float2bfloat16(p0 - __bfloat162float(h0));
                Alo[t * SA + lane + 32] = __float2bfloat16(p1 - __bfloat162float(h1));
            }
        }
    }
    __syncthreads();

    // ---- phase 2: warp w owns token rows [16w, 16w+16) ----
    const int g  = lane >> 2;
    const int t4 = lane & 3;
    const int rb = w * 16;

    uint32_t ahi[4][4], alo[4][4];
    #pragma unroll
    for (int kc = 0; kc < 4; kc++) {
        int kb = kc * 16 + 2 * t4;
        ahi[kc][0] = *(const uint32_t*)&Ahi[(rb + g)     * SA + kb];
        ahi[kc][1] = *(const uint32_t*)&Ahi[(rb + g + 8) * SA + kb];
        ahi[kc][2] = *(const uint32_t*)&Ahi[(rb + g)     * SA + kb + 8];
        ahi[kc][3] = *(const uint32_t*)&Ahi[(rb + g + 8) * SA + kb + 8];
        alo[kc][0] = *(const uint32_t*)&Alo[(rb + g)     * SA + kb];
        alo[kc][1] = *(const uint32_t*)&Alo[(rb + g + 8) * SA + kb];
        alo[kc][2] = *(const uint32_t*)&Alo[(rb + g)     * SA + kb + 8];
        alo[kc][3] = *(const uint32_t*)&Alo[(rb + g + 8) * SA + kb + 8];
    }

    float v0 = 0.f, v1 = 0.f;

    #pragma unroll
    for (int nc = 0; nc < 8; nc++) {
        const int nb = nc * 8;
        float d0 = 0.f, d1 = 0.f, d2 = 0.f, d3 = 0.f;

        #pragma unroll
        for (int kc = 0; kc < 4; kc++) {
            int kb = kc * 16 + 2 * t4;
            uint32_t bh0 = *(const uint32_t*)&Bhi[(nb + g) * SB + kb];
            uint32_t bh1 = *(const uint32_t*)&Bhi[(nb + g) * SB + kb + 8];
            uint32_t bl0 = *(const uint32_t*)&Blo[(nb + g) * SB + kb];
            uint32_t bl1 = *(const uint32_t*)&Blo[(nb + g) * SB + kb + 8];
            MMA16816(d0, d1, d2, d3, ahi[kc], bh0, bh1);
            MMA16816(d0, d1, d2, d3, ahi[kc], bl0, bl1);
            MMA16816(d0, d1, d2, d3, alo[kc], bh0, bh1);
        }

        const int c0 = nb + 2 * t4;
        uint32_t phA = *(const uint32_t*)&Ahi[(rb + g + 1) * SA + c0];
        uint32_t plA = *(const uint32_t*)&Alo[(rb + g + 1) * SA + c0];
        uint32_t phB = *(const uint32_t*)&Ahi[(rb + g + 9) * SA + c0];
        uint32_t plB = *(const uint32_t*)&Alo[(rb + g + 9) * SA + c0];
        __nv_bfloat162 hA = *(__nv_bfloat162*)&phA, lA = *(__nv_bfloat162*)&plA;
        __nv_bfloat162 hB = *(__nv_bfloat162*)&phB, lB = *(__nv_bfloat162*)&plB;
        float pxA = __low2float(hA)  + __low2float(lA);
        float pyA = __high2float(hA) + __high2float(lA);
        float pxB = __low2float(hB)  + __low2float(lB);
        float pyB = __high2float(hB) + __high2float(lB);

        v0 = fmaf(d0, pxA, v0); v0 = fmaf(d1, pyA, v0);
        v1 = fmaf(d2, pxB, v1); v1 = fmaf(d3, pyB, v1);
    }

    v0 += __shfl_xor_sync(0xffffffffu, v0, 1);
    v0 += __shfl_xor_sync(0xffffffffu, v0, 2);
    v1 += __shfl_xor_sync(0xffffffffu, v1, 1);
    v1 += __shfl_xor_sync(0xffffffffu, v1, 2);

    if (t4 == 0) {
        float* outp = out + (size_t)b * (SS - 1) + t0;
        int i0 = rb + g, i1 = rb + g + 8;
        if (i0 < nout) outp[i0] = v0;
        if (i1 < nout) outp[i1] = v1;
    }
}

extern "C" void kernel_launch(void* const* d_in, const int* in_sizes, int n_in,
                              void* d_out, int out_size)
{
    const float* logits = (const float*)d_in[0];
    const float* M      = (const float*)d_in[1];
    float* out          = (float*)d_out;

    cudaFuncSetAttribute(pk_kernel, cudaFuncAttributeMaxDynamicSharedMemorySize, SMEM_TOTAL);
    dim3 grid(SS / TILE, BB);
    pk_kernel<<<grid, THREADS, SMEM_TOTAL>>>(logits, M, out);
}

// round 9
// speedup vs baseline: 2.6382x; 1.6010x over previous
#include <cuda_runtime.h>
#include <cuda_bf16.h>
#include <cstdint>

#define BB 128
#define SS 4096
#define CC 64
#define TILE 128
#define NW 8
#define THREADS (NW * 32)

#define SA 72            // bf16 stride: 144B rows -> bank step 4 -> conflict-free frags
#define SB 72
#define OFF_AHI 0
#define OFF_ALO 18576    // 129*72*2
#define OFF_BHI 37152
#define OFF_BLO 46368    // + 64*72*2 = 9216
#define SMEM_TOTAL 55584

#define MMA16816(d0,d1,d2,d3,a,b0,b1)                                        \
    asm volatile("mma.sync.aligned.m16n8k16.row.col.f32.bf16.bf16.f32 "      \
        "{%0,%1,%2,%3}, {%4,%5,%6,%7}, {%8,%9}, {%0,%1,%2,%3};"              \
        : "+f"(d0), "+f"(d1), "+f"(d2), "+f"(d3)                              \
        : "r"((a)[0]), "r"((a)[1]), "r"((a)[2]), "r"((a)[3]), "r"(b0), "r"(b1))

// ---- packed f32x2 ops ----
__device__ __forceinline__ float2 ffma2(float2 a, float2 b, float2 c) {
    float2 d;
    asm("{ .reg .b64 ra, rb, rc, rd;\n\t"
        "mov.b64 ra, {%2, %3}; mov.b64 rb, {%4, %5}; mov.b64 rc, {%6, %7};\n\t"
        "fma.rn.f32x2 rd, ra, rb, rc;\n\t"
        "mov.b64 {%0, %1}, rd; }"
        : "=f"(d.x), "=f"(d.y)
        : "f"(a.x), "f"(a.y), "f"(b.x), "f"(b.y), "f"(c.x), "f"(c.y));
    return d;
}
__device__ __forceinline__ float2 fmul2(float2 a, float2 b) {
    float2 d;
    asm("{ .reg .b64 ra, rb, rd;\n\t"
        "mov.b64 ra, {%2, %3}; mov.b64 rb, {%4, %5};\n\t"
        "mul.rn.f32x2 rd, ra, rb;\n\t"
        "mov.b64 {%0, %1}, rd; }"
        : "=f"(d.x), "=f"(d.y)
        : "f"(a.x), "f"(a.y), "f"(b.x), "f"(b.y));
    return d;
}

// paired exp(x) on FMA/ALU pipes (no MUFU)
__device__ __forceinline__ float2 fast_exp2x(float2 x) {
    const float L2E   = 1.4426950408889634f;
    const float MAGIC = 12582912.0f;               // 1.5 * 2^23
    float2 y = fmul2(x, make_float2(L2E, L2E));
    float2 t = ffma2(y, make_float2(1.f, 1.f), make_float2(MAGIC, MAGIC));
    float2 n = ffma2(t, make_float2(1.f, 1.f), make_float2(-MAGIC, -MAGIC));
    float2 f = ffma2(n, make_float2(-1.f, -1.f), y);
    float2 p = make_float2(1.3333558146428443e-3f, 1.3333558146428443e-3f);
    p = ffma2(p, f, make_float2(9.6181291076284772e-3f, 9.6181291076284772e-3f));
    p = ffma2(p, f, make_float2(5.5504108664798463e-2f, 5.5504108664798463e-2f));
    p = ffma2(p, f, make_float2(2.4022650695910072e-1f, 2.4022650695910072e-1f));
    p = ffma2(p, f, make_float2(6.9314718055994531e-1f, 6.9314718055994531e-1f));
    p = ffma2(p, f, make_float2(1.0f, 1.0f));
    float2 sc;
    sc.x = __int_as_float((__float_as_int(t.x) - 0x4B400000 + 127) << 23);
    sc.y = __int_as_float((__float_as_int(t.y) - 0x4B400000 + 127) << 23);
    return fmul2(p, sc);
}

__global__ __launch_bounds__(THREADS, 3) void pk_kernel(
    const float* __restrict__ logits,
    const float* __restrict__ M,
    float* __restrict__ out)
{
    extern __shared__ char dsm[];
    __nv_bfloat16* Ahi = (__nv_bfloat16*)(dsm + OFF_AHI);
    __nv_bfloat16* Alo = (__nv_bfloat16*)(dsm + OFF_ALO);
    __nv_bfloat16* Bhi = (__nv_bfloat16*)(dsm + OFF_BHI);
    __nv_bfloat16* Blo = (__nv_bfloat16*)(dsm + OFF_BLO);

    const int b    = blockIdx.y;
    const int t0   = blockIdx.x * TILE;
    const int tid  = threadIdx.x;
    const int w    = tid >> 5;
    const int lane = tid & 31;

    const int ntok = min(TILE + 1, SS - t0);
    const int nout = min(TILE, SS - 1 - t0);

    // ---- stage B = M^T as bf16 hi/lo ----
    for (int idx = tid; idx < CC * CC; idx += THREADS) {
        int k = idx >> 6, n = idx & 63;
        float v = M[idx];
        __nv_bfloat16 h = __float2bfloat16(v);
        __nv_bfloat16 l = __float2bfloat16(v - __bfloat162float(h));
        Bhi[n * SB + k] = h;
        Blo[n * SB + k] = l;
    }

    // ---- phase 1: log-softmax, warp-per-token, 4 tokens batched ----
    // lane owns classes (2*lane, 2*lane+1) via float2 loads
    const float2* lg2 = (const float2*)(logits + ((size_t)b * SS + t0) * CC);
    for (int base = w * 4; base < ntok; base += NW * 4) {
        float2 x[4];
        #pragma unroll
        for (int j = 0; j < 4; j++) {
            int t = base + j;
            int tt = (t < ntok) ? t : (ntok - 1);
            x[j] = lg2[tt * 32 + lane];
        }

        float s[4];
        #pragma unroll
        for (int j = 0; j < 4; j++) {
            float2 e = fast_exp2x(x[j]);
            s[j] = e.x + e.y;
        }
        #pragma unroll
        for (int o = 16; o; o >>= 1) {
            #pragma unroll
            for (int j = 0; j < 4; j++)
                s[j] += __shfl_xor_sync(0xffffffffu, s[j], o);
        }

        #pragma unroll
        for (int j = 0; j < 4; j++) {
            int t = base + j;
            if (t < ntok) {
                float lse = __logf(s[j]);
                float p0 = x[j].x - lse, p1 = x[j].y - lse;
                __nv_bfloat162 h = __floats2bfloat162_rn(p0, p1);
                float l0 = p0 - __bfloat162float(h.x);
                float l1 = p1 - __bfloat162float(h.y);
                __nv_bfloat162 l = __floats2bfloat162_rn(l0, l1);
                *(uint32_t*)&Ahi[t * SA + 2 * lane] = *(uint32_t*)&h;
                *(uint32_t*)&Alo[t * SA + 2 * lane] = *(uint32_t*)&l;
            }
        }
    }
    __syncthreads();

    // ---- phase 2: warp w owns token rows [16w, 16w+16) ----
    const int g  = lane >> 2;
    const int t4 = lane & 3;
    const int rb = w * 16;

    uint32_t ahi[4][4], alo[4][4];
    #pragma unroll
    for (int kc = 0; kc < 4; kc++) {
        int kb = kc * 16 + 2 * t4;
        ahi[kc][0] = *(const uint32_t*)&Ahi[(rb + g)     * SA + kb];
        ahi[kc][1] = *(const uint32_t*)&Ahi[(rb + g + 8) * SA + kb];
        ahi[kc][2] = *(const uint32_t*)&Ahi[(rb + g)     * SA + kb + 8];
        ahi[kc][3] = *(const uint32_t*)&Ahi[(rb + g + 8) * SA + kb + 8];
        alo[kc][0] = *(const uint32_t*)&Alo[(rb + g)     * SA + kb];
        alo[kc][1] = *(const uint32_t*)&Alo[(rb + g + 8) * SA + kb];
        alo[kc][2] = *(const uint32_t*)&Alo[(rb + g)     * SA + kb + 8];
        alo[kc][3] = *(const uint32_t*)&Alo[(rb + g + 8) * SA + kb + 8];
    }

    float v0 = 0.f, v1 = 0.f;

    #pragma unroll
    for (int nc = 0; nc < 8; nc++) {
        const int nb = nc * 8;
        float d0 = 0.f, d1 = 0.f, d2 = 0.f, d3 = 0.f;

        #pragma unroll
        for (int kc = 0; kc < 4; kc++) {
            int kb = kc * 16 + 2 * t4;
            uint32_t bh0 = *(const uint32_t*)&Bhi[(nb + g) * SB + kb];
            uint32_t bh1 = *(const uint32_t*)&Bhi[(nb + g) * SB + kb + 8];
            uint32_t bl0 = *(const uint32_t*)&Blo[(nb + g) * SB + kb];
            uint32_t bl1 = *(const uint32_t*)&Blo[(nb + g) * SB + kb + 8];
            MMA16816(d0, d1, d2, d3, ahi[kc], bh0, bh1);
            MMA16816(d0, d1, d2, d3, ahi[kc], bl0, bl1);
            MMA16816(d0, d1, d2, d3, alo[kc], bh0, bh1);
        }

        const int c0 = nb + 2 * t4;
        uint32_t phA = *(const uint32_t*)&Ahi[(rb + g + 1) * SA + c0];
        uint32_t plA = *(const uint32_t*)&Alo[(rb + g + 1) * SA + c0];
        uint32_t phB = *(const uint32_t*)&Ahi[(rb + g + 9) * SA + c0];
        uint32_t plB = *(const uint32_t*)&Alo[(rb + g + 9) * SA + c0];
        __nv_bfloat162 hA = *(__nv_bfloat162*)&phA, lA = *(__nv_bfloat162*)&plA;
        __nv_bfloat162 hB = *(__nv_bfloat162*)&phB, lB = *(__nv_bfloat162*)&plB;
        float pxA = __low2float(hA)  + __low2float(lA);
        float pyA = __high2float(hA) + __high2float(lA);
        float pxB = __low2float(hB)  + __low2float(lB);
        float pyB = __high2float(hB) + __high2float(lB);

        v0 = fmaf(d0, pxA, v0); v0 = fmaf(d1, pyA, v0);
        v1 = fmaf(d2, pxB, v1); v1 = fmaf(d3, pyB, v1);
    }

    v0 += __shfl_xor_sync(0xffffffffu, v0, 1);
    v0 += __shfl_xor_sync(0xffffffffu, v0, 2);
    v1 += __shfl_xor_sync(0xffffffffu, v1, 1);
    v1 += __shfl_xor_sync(0xffffffffu, v1, 2);

    if (t4 == 0) {
        float* outp = out + (size_t)b * (SS - 1) + t0;
        int i0 = rb + g, i1 = rb + g + 8;
        if (i0 < nout) outp[i0] = v0;
        if (i1 < nout) outp[i1] = v1;
    }
}

extern "C" void kernel_launch(void* const* d_in, const int* in_sizes, int n_in,
                              void* d_out, int out_size)
{
    const float* logits = (const float*)d_in[0];
    const float* M      = (const float*)d_in[1];
    float* out          = (float*)d_out;

    cudaFuncSetAttribute(pk_kernel, cudaFuncAttributeMaxDynamicSharedMemorySize, SMEM_TOTAL);
    dim3 grid(SS / TILE, BB);
    pk_kernel<<<grid, THREADS, SMEM_TOTAL>>>(logits, M, out);
}

// round 10
// speedup vs baseline: 3.1062x; 1.1774x over previous
#include <cuda_runtime.h>
#include <cuda_bf16.h>
#include <cstdint>

#define BB 128
#define SS 4096
#define CC 64
#define TILE 128
#define NW 8
#define THREADS (NW * 32)

#define SA 72            // bf16 stride: 144B rows -> bank step 4 -> conflict-free
#define SB 72
#define OFF_AHI 0
#define OFF_ALO 18576    // 129*72*2
#define OFF_BHI 37152
#define OFF_BLO 46368    // + 64*72*2 = 9216
#define SMEM_TOTAL 55584

#define MMA16816(d,a,b0,b1)                                                   \
    asm volatile("mma.sync.aligned.m16n8k16.row.col.f32.bf16.bf16.f32 "       \
        "{%0,%1,%2,%3}, {%4,%5,%6,%7}, {%8,%9}, {%0,%1,%2,%3};"               \
        : "+f"((d)[0]), "+f"((d)[1]), "+f"((d)[2]), "+f"((d)[3])              \
        : "r"((a)[0]), "r"((a)[1]), "r"((a)[2]), "r"((a)[3]), "r"(b0), "r"(b1))

#define LDSM4(r0,r1,r2,r3,addr)                                               \
    asm volatile("ldmatrix.sync.aligned.m8n8.x4.shared.b16 {%0,%1,%2,%3}, [%4];" \
        : "=r"(r0), "=r"(r1), "=r"(r2), "=r"(r3) : "r"(addr))

static __device__ __forceinline__ uint32_t smem_u32(const void* p) {
    uint32_t a;
    asm("{ .reg .u64 t; cvta.to.shared.u64 t, %1; cvt.u32.u64 %0, t; }" : "=r"(a) : "l"(p));
    return a;
}

// ---- packed f32x2 ops ----
__device__ __forceinline__ float2 ffma2(float2 a, float2 b, float2 c) {
    float2 d;
    asm("{ .reg .b64 ra, rb, rc, rd;\n\t"
        "mov.b64 ra, {%2, %3}; mov.b64 rb, {%4, %5}; mov.b64 rc, {%6, %7};\n\t"
        "fma.rn.f32x2 rd, ra, rb, rc;\n\t"
        "mov.b64 {%0, %1}, rd; }"
        : "=f"(d.x), "=f"(d.y)
        : "f"(a.x), "f"(a.y), "f"(b.x), "f"(b.y), "f"(c.x), "f"(c.y));
    return d;
}
__device__ __forceinline__ float2 fmul2(float2 a, float2 b) {
    float2 d;
    asm("{ .reg .b64 ra, rb, rd;\n\t"
        "mov.b64 ra, {%2, %3}; mov.b64 rb, {%4, %5};\n\t"
        "mul.rn.f32x2 rd, ra, rb;\n\t"
        "mov.b64 {%0, %1}, rd; }"
        : "=f"(d.x), "=f"(d.y)
        : "f"(a.x), "f"(a.y), "f"(b.x), "f"(b.y));
    return d;
}

// paired exp(x) on FMA/ALU pipes (no MUFU)
__device__ __forceinline__ float2 fast_exp2x(float2 x) {
    const float L2E   = 1.4426950408889634f;
    const float MAGIC = 12582912.0f;               // 1.5 * 2^23
    float2 y = fmul2(x, make_float2(L2E, L2E));
    float2 t = ffma2(y, make_float2(1.f, 1.f), make_float2(MAGIC, MAGIC));
    float2 n = ffma2(t, make_float2(1.f, 1.f), make_float2(-MAGIC, -MAGIC));
    float2 f = ffma2(n, make_float2(-1.f, -1.f), y);
    float2 p = make_float2(1.3333558146428443e-3f, 1.3333558146428443e-3f);
    p = ffma2(p, f, make_float2(9.6181291076284772e-3f, 9.6181291076284772e-3f));
    p = ffma2(p, f, make_float2(5.5504108664798463e-2f, 5.5504108664798463e-2f));
    p = ffma2(p, f, make_float2(2.4022650695910072e-1f, 2.4022650695910072e-1f));
    p = ffma2(p, f, make_float2(6.9314718055994531e-1f, 6.9314718055994531e-1f));
    p = ffma2(p, f, make_float2(1.0f, 1.0f));
    float2 sc;
    sc.x = __int_as_float((__float_as_int(t.x) - 0x4B400000 + 127) << 23);
    sc.y = __int_as_float((__float_as_int(t.y) - 0x4B400000 + 127) << 23);
    return fmul2(p, sc);
}

__global__ __launch_bounds__(THREADS, 3) void pk_kernel(
    const float* __restrict__ logits,
    const float* __restrict__ M,
    float* __restrict__ out)
{
    extern __shared__ char dsm[];
    __nv_bfloat16* Ahi = (__nv_bfloat16*)(dsm + OFF_AHI);
    __nv_bfloat16* Alo = (__nv_bfloat16*)(dsm + OFF_ALO);
    __nv_bfloat16* Bhi = (__nv_bfloat16*)(dsm + OFF_BHI);
    __nv_bfloat16* Blo = (__nv_bfloat16*)(dsm + OFF_BLO);
    const uint32_t sb = smem_u32(dsm);

    const int b    = blockIdx.y;
    const int t0   = blockIdx.x * TILE;
    const int tid  = threadIdx.x;
    const int w    = tid >> 5;
    const int lane = tid & 31;

    const int ntok = min(TILE + 1, SS - t0);
    const int nout = min(TILE, SS - 1 - t0);

    // ---- stage B = M^T as bf16 hi/lo ----
    for (int idx = tid; idx < CC * CC; idx += THREADS) {
        int k = idx >> 6, n = idx & 63;
        float v = M[idx];
        __nv_bfloat16 h = __float2bfloat16(v);
        __nv_bfloat16 l = __float2bfloat16(v - __bfloat162float(h));
        Bhi[n * SB + k] = h;
        Blo[n * SB + k] = l;
    }

    // ---- phase 1: log-softmax; 16 lanes per token, 2 tokens per warp-row ----
    const float4* lg4 = (const float4*)(logits + ((size_t)b * SS + t0) * CC);
    const int half = lane >> 4;   // which token of the pair
    const int qi   = lane & 15;   // class quad: owns classes 4qi..4qi+3

    for (int tb = w * 8; tb < ntok; tb += NW * 8) {
        float4 x[4];
        int tk[4];
        #pragma unroll
        for (int j = 0; j < 4; j++) {
            int t = tb + 2 * j + half;
            tk[j] = t;
            int tt = (t < ntok) ? t : (ntok - 1);
            x[j] = lg4[tt * 16 + qi];
        }

        float s[4];
        #pragma unroll
        for (int j = 0; j < 4; j++) {
            float2 e0 = fast_exp2x(make_float2(x[j].x, x[j].y));
            float2 e1 = fast_exp2x(make_float2(x[j].z, x[j].w));
            s[j] = (e0.x + e0.y) + (e1.x + e1.y);
        }
        #pragma unroll
        for (int o = 8; o; o >>= 1) {
            #pragma unroll
            for (int j = 0; j < 4; j++)
                s[j] += __shfl_xor_sync(0xffffffffu, s[j], o);
        }

        #pragma unroll
        for (int j = 0; j < 4; j++) {
            if (tk[j] < ntok) {
                float lse = __logf(s[j]);
                float p0 = x[j].x - lse, p1 = x[j].y - lse;
                float p2 = x[j].z - lse, p3 = x[j].w - lse;
                __nv_bfloat162 h01 = __floats2bfloat162_rn(p0, p1);
                __nv_bfloat162 h23 = __floats2bfloat162_rn(p2, p3);
                __nv_bfloat162 l01 = __floats2bfloat162_rn(p0 - __bfloat162float(h01.x),
                                                           p1 - __bfloat162float(h01.y));
                __nv_bfloat162 l23 = __floats2bfloat162_rn(p2 - __bfloat162float(h23.x),
                                                           p3 - __bfloat162float(h23.y));
                uint2 hv = make_uint2(*(uint32_t*)&h01, *(uint32_t*)&h23);
                uint2 lv = make_uint2(*(uint32_t*)&l01, *(uint32_t*)&l23);
                *(uint2*)&Ahi[tk[j] * SA + 4 * qi] = hv;
                *(uint2*)&Alo[tk[j] * SA + 4 * qi] = lv;
            }
        }
    }
    __syncthreads();

    // ---- phase 2: warp w owns token rows [16w, 16w+16); ldmatrix everywhere ----
    const int g  = lane >> 2;
    const int t4 = lane & 3;
    const int rb = w * 16;
    const int q  = lane >> 3;   // ldmatrix matrix index
    const int r  = lane & 7;    // ldmatrix row-within-matrix

    // lane-invariant byte offsets for ldmatrix addressing
    const uint32_t aAddr = sb + (uint32_t)(((rb + r + (q & 1) * 8) * SA + (q >> 1) * 8) * 2);
    const uint32_t bAddr = sb + OFF_BHI + (uint32_t)(((r + (q >> 1) * 8) * SB + (q & 1) * 8) * 2);
    const uint32_t eAddr = sb + (uint32_t)(((rb + 1 + r + (q & 1) * 8) * SA + (q >> 1) * 8) * 2);

    // A fragments (hi & lo) for all 4 k-chunks
    uint32_t ahi[4][4], alo[4][4];
    #pragma unroll
    for (int kc = 0; kc < 4; kc++) {
        LDSM4(ahi[kc][0], ahi[kc][1], ahi[kc][2], ahi[kc][3], aAddr + OFF_AHI + kc * 32);
        LDSM4(alo[kc][0], alo[kc][1], alo[kc][2], alo[kc][3], aAddr + OFF_ALO + kc * 32);
    }

    float v0 = 0.f, v1 = 0.f;

    #pragma unroll
    for (int ncp = 0; ncp < 4; ncp++) {                   // nc pair: cols 16ncp..16ncp+15
        float d0[4] = {0.f, 0.f, 0.f, 0.f};               // nc = 2ncp
        float d1[4] = {0.f, 0.f, 0.f, 0.f};               // nc = 2ncp+1
        const uint32_t bOff = bAddr + (uint32_t)(ncp * 16 * SB * 2);

        #pragma unroll
        for (int kc = 0; kc < 4; kc++) {
            uint32_t bh0, bh1, bh2, bh3, bl0, bl1, bl2, bl3;
            LDSM4(bh0, bh1, bh2, bh3, bOff + kc * 32);                         // Bhi
            LDSM4(bl0, bl1, bl2, bl3, bOff + (OFF_BLO - OFF_BHI) + kc * 32);   // Blo
            MMA16816(d0, ahi[kc], bh0, bh1);
            MMA16816(d0, ahi[kc], bl0, bl1);
            MMA16816(d0, alo[kc], bh0, bh1);
            MMA16816(d1, ahi[kc], bh2, bh3);
            MMA16816(d1, ahi[kc], bl2, bl3);
            MMA16816(d1, alo[kc], bh2, bh3);
        }

        // epilogue fragment: p_{i+1} rows rb+1..rb+16, cols 16ncp..16ncp+15
        uint32_t ph[4], pl[4];
        LDSM4(ph[0], ph[1], ph[2], ph[3], eAddr + OFF_AHI + ncp * 32);
        LDSM4(pl[0], pl[1], pl[2], pl[3], eAddr + OFF_ALO + ncp * 32);

        #pragma unroll
        for (int m = 0; m < 4; m++) {
            __nv_bfloat162 h = *(__nv_bfloat162*)&ph[m];
            __nv_bfloat162 l = *(__nv_bfloat162*)&pl[m];
            float px = __low2float(h)  + __low2float(l);
            float py = __high2float(h) + __high2float(l);
            const float* dd = (m & 2) ? d1 : d0;          // m2,m3 -> nc+1
            int base = (m & 1) ? 2 : 0;                    // m1,m3 -> rows +8 -> v1
            if (m & 1) {
                v1 = fmaf(dd[base],     px, v1);
                v1 = fmaf(dd[base + 1], py, v1);
            } else {
                v0 = fmaf(dd[0], px, v0);
                v0 = fmaf(dd[1], py, v0);
            }
        }
    }

    v0 += __shfl_xor_sync(0xffffffffu, v0, 1);
    v0 += __shfl_xor_sync(0xffffffffu, v0, 2);
    v1 += __shfl_xor_sync(0xffffffffu, v1, 1);
    v1 += __shfl_xor_sync(0xffffffffu, v1, 2);

    if (t4 == 0) {
        float* outp = out + (size_t)b * (SS - 1) + t0;
        int i0 = rb + g, i1 = rb + g + 8;
        if (i0 < nout) outp[i0] = v0;
        if (i1 < nout) outp[i1] = v1;
    }
}

extern "C" void kernel_launch(void* const* d_in, const int* in_sizes, int n_in,
                              void* d_out, int out_size)
{
    const float* logits = (const float*)d_in[0];
    const float* M      = (const float*)d_in[1];
    float* out          = (float*)d_out;

    cudaFuncSetAttribute(pk_kernel, cudaFuncAttributeMaxDynamicSharedMemorySize, SMEM_TOTAL);
    dim3 grid(SS / TILE, BB);
    pk_kernel<<<grid, THREADS, SMEM_TOTAL>>>(logits, M, out);
}

// round 11
// speedup vs baseline: 3.1641x; 1.0186x over previous
#include <cuda_runtime.h>
#include <cuda_bf16.h>
#include <cstdint>

#define BB 128
#define SS 4096
#define CC 64
#define TILE 128
#define NW 8
#define THREADS (NW * 32)

#define SA 72            // bf16 stride: 144B rows -> conflict-free
#define SB 72
#define OFF_A 0          // [129][72] bf16 logits(hi) = 18576
#define OFF_B 18576      // [64][72]  bf16 M^T        = 9216
#define OFF_U 27792      // 64 f32 row sums u = M@1
#define OFF_W 28048      // 64 f32 col sums w = M^T@1
#define OFF_T 28304      // [129] float4 (lse, du, dw, 0)
#define OFF_MS 30368     // 1 f32 sum(M)
#define SMEM_TOTAL 30384

#define MMA16816(d,a,b0,b1)                                                   \
    asm volatile("mma.sync.aligned.m16n8k16.row.col.f32.bf16.bf16.f32 "       \
        "{%0,%1,%2,%3}, {%4,%5,%6,%7}, {%8,%9}, {%0,%1,%2,%3};"               \
        : "+f"((d)[0]), "+f"((d)[1]), "+f"((d)[2]), "+f"((d)[3])              \
        : "r"((a)[0]), "r"((a)[1]), "r"((a)[2]), "r"((a)[3]), "r"(b0), "r"(b1))

#define LDSM4(r0,r1,r2,r3,addr)                                               \
    asm volatile("ldmatrix.sync.aligned.m8n8.x4.shared.b16 {%0,%1,%2,%3}, [%4];" \
        : "=r"(r0), "=r"(r1), "=r"(r2), "=r"(r3) : "r"(addr))

static __device__ __forceinline__ uint32_t smem_u32(const void* p) {
    uint32_t a;
    asm("{ .reg .u64 t; cvta.to.shared.u64 t, %1; cvt.u32.u64 %0, t; }" : "=r"(a) : "l"(p));
    return a;
}

// ---- packed f32x2 ops ----
__device__ __forceinline__ float2 ffma2(float2 a, float2 b, float2 c) {
    float2 d;
    asm("{ .reg .b64 ra, rb, rc, rd;\n\t"
        "mov.b64 ra, {%2, %3}; mov.b64 rb, {%4, %5}; mov.b64 rc, {%6, %7};\n\t"
        "fma.rn.f32x2 rd, ra, rb, rc;\n\t"
        "mov.b64 {%0, %1}, rd; }"
        : "=f"(d.x), "=f"(d.y)
        : "f"(a.x), "f"(a.y), "f"(b.x), "f"(b.y), "f"(c.x), "f"(c.y));
    return d;
}
__device__ __forceinline__ float2 fmul2(float2 a, float2 b) {
    float2 d;
    asm("{ .reg .b64 ra, rb, rd;\n\t"
        "mov.b64 ra, {%2, %3}; mov.b64 rb, {%4, %5};\n\t"
        "mul.rn.f32x2 rd, ra, rb;\n\t"
        "mov.b64 {%0, %1}, rd; }"
        : "=f"(d.x), "=f"(d.y)
        : "f"(a.x), "f"(a.y), "f"(b.x), "f"(b.y));
    return d;
}

// paired exp(x) on FMA/ALU pipes (no MUFU)
__device__ __forceinline__ float2 fast_exp2x(float2 x) {
    const float L2E   = 1.4426950408889634f;
    const float MAGIC = 12582912.0f;               // 1.5 * 2^23
    float2 y = fmul2(x, make_float2(L2E, L2E));
    float2 t = ffma2(y, make_float2(1.f, 1.f), make_float2(MAGIC, MAGIC));
    float2 n = ffma2(t, make_float2(1.f, 1.f), make_float2(-MAGIC, -MAGIC));
    float2 f = ffma2(n, make_float2(-1.f, -1.f), y);
    float2 p = make_float2(1.3333558146428443e-3f, 1.3333558146428443e-3f);
    p = ffma2(p, f, make_float2(9.6181291076284772e-3f, 9.6181291076284772e-3f));
    p = ffma2(p, f, make_float2(5.5504108664798463e-2f, 5.5504108664798463e-2f));
    p = ffma2(p, f, make_float2(2.4022650695910072e-1f, 2.4022650695910072e-1f));
    p = ffma2(p, f, make_float2(6.9314718055994531e-1f, 6.9314718055994531e-1f));
    p = ffma2(p, f, make_float2(1.0f, 1.0f));
    float2 sc;
    sc.x = __int_as_float((__float_as_int(t.x) - 0x4B400000 + 127) << 23);
    sc.y = __int_as_float((__float_as_int(t.y) - 0x4B400000 + 127) << 23);
    return fmul2(p, sc);
}

__global__ __launch_bounds__(THREADS, 4) void pk_kernel(
    const float* __restrict__ logits,
    const float* __restrict__ M,
    float* __restrict__ out)
{
    extern __shared__ char dsm[];
    __nv_bfloat16* A   = (__nv_bfloat16*)(dsm + OFF_A);
    __nv_bfloat16* Bm  = (__nv_bfloat16*)(dsm + OFF_B);
    float*         su  = (float*)(dsm + OFF_U);
    float*         sw  = (float*)(dsm + OFF_W);
    float4*        tbl = (float4*)(dsm + OFF_T);
    const uint32_t sb  = smem_u32(dsm);

    const int b    = blockIdx.y;
    const int t0   = blockIdx.x * TILE;
    const int tid  = threadIdx.x;
    const int w    = tid >> 5;
    const int lane = tid & 31;

    const int ntok = min(TILE + 1, SS - t0);
    const int nout = min(TILE, SS - 1 - t0);

    // ---- stage B = M^T (bf16), u = M@1, w = M^T@1 ----
    for (int idx = tid; idx < CC * CC; idx += THREADS) {
        int k = idx >> 6, n = idx & 63;
        Bm[n * SB + k] = __float2bfloat16(M[idx]);
    }
    if (tid < 64) {
        const float4* r = (const float4*)(M + tid * CC);
        float s = 0.f;
        #pragma unroll
        for (int i = 0; i < 16; i++) { float4 v = r[i]; s += (v.x + v.y) + (v.z + v.w); }
        su[tid] = s;
    } else if (tid < 128) {
        int c = tid - 64;
        float s = 0.f;
        #pragma unroll 8
        for (int d = 0; d < 64; d++) s += M[d * CC + c];
        sw[c] = s;
    }
    __syncthreads();

    if (tid == 0) {
        float s = 0.f;
        #pragma unroll
        for (int i = 0; i < 64; i++) s += su[i];
        *(float*)(dsm + OFF_MS) = s;    // consumed after next barrier
    }

    // ---- phase 1: per-token lse, du = u.x, dw = w.x; store x as bf16 ----
    const float4* lg4 = (const float4*)(logits + ((size_t)b * SS + t0) * CC);
    const int half = lane >> 4;
    const int qi   = lane & 15;
    const float4 u4 = ((const float4*)su)[qi];
    const float4 w4 = ((const float4*)sw)[qi];

    for (int tb = w * 8; tb < ntok; tb += NW * 8) {
        float4 x[4];
        int tk[4];
        #pragma unroll
        for (int j = 0; j < 4; j++) {
            int t = tb + 2 * j + half;
            tk[j] = t;
            int tt = (t < ntok) ? t : (ntok - 1);
            x[j] = lg4[tt * 16 + qi];
        }

        float s[4], du[4], dw[4];
        #pragma unroll
        for (int j = 0; j < 4; j++) {
            float2 e0 = fast_exp2x(make_float2(x[j].x, x[j].y));
            float2 e1 = fast_exp2x(make_float2(x[j].z, x[j].w));
            s[j]  = (e0.x + e0.y) + (e1.x + e1.y);
            du[j] = fmaf(x[j].x, u4.x, fmaf(x[j].y, u4.y, fmaf(x[j].z, u4.z, x[j].w * u4.w)));
            dw[j] = fmaf(x[j].x, w4.x, fmaf(x[j].y, w4.y, fmaf(x[j].z, w4.z, x[j].w * w4.w)));
        }
        #pragma unroll
        for (int o = 8; o; o >>= 1) {
            #pragma unroll
            for (int j = 0; j < 4; j++) {
                s[j]  += __shfl_xor_sync(0xffffffffu, s[j],  o);
                du[j] += __shfl_xor_sync(0xffffffffu, du[j], o);
                dw[j] += __shfl_xor_sync(0xffffffffu, dw[j], o);
            }
        }

        #pragma unroll
        for (int j = 0; j < 4; j++) {
            if (tk[j] < ntok) {
                if (qi == 0) {
                    float lse = __logf(s[j]);
                    tbl[tk[j]] = make_float4(lse, du[j], dw[j], 0.f);
                }
                __nv_bfloat162 h01 = __floats2bfloat162_rn(x[j].x, x[j].y);
                __nv_bfloat162 h23 = __floats2bfloat162_rn(x[j].z, x[j].w);
                uint2 hv = make_uint2(*(uint32_t*)&h01, *(uint32_t*)&h23);
                *(uint2*)&A[tk[j] * SA + 4 * qi] = hv;
            }
        }
    }
    __syncthreads();

    // ---- phase 2: warp w owns token rows [16w, 16w+16) ----
    const int g  = lane >> 2;
    const int t4 = lane & 3;
    const int rb = w * 16;
    const int q  = lane >> 3;
    const int r  = lane & 7;

    const uint32_t aAddr = sb + (uint32_t)(((rb + r + (q & 1) * 8) * SA + (q >> 1) * 8) * 2);
    const uint32_t bAddr = sb + OFF_B + (uint32_t)(((r + (q >> 1) * 8) * SB + (q & 1) * 8) * 2);
    const uint32_t eAddr = sb + (uint32_t)(((rb + 1 + r + (q & 1) * 8) * SA + (q >> 1) * 8) * 2);

    uint32_t af[4][4];
    #pragma unroll
    for (int kc = 0; kc < 4; kc++)
        LDSM4(af[kc][0], af[kc][1], af[kc][2], af[kc][3], aAddr + kc * 32);

    float v0 = 0.f, v1 = 0.f;

    #pragma unroll
    for (int ncp = 0; ncp < 4; ncp++) {
        float d0[4] = {0.f, 0.f, 0.f, 0.f};
        float d1[4] = {0.f, 0.f, 0.f, 0.f};
        const uint32_t bOff = bAddr + (uint32_t)(ncp * 16 * SB * 2);

        #pragma unroll
        for (int kc = 0; kc < 4; kc++) {
            uint32_t b0, b1, b2, b3;
            LDSM4(b0, b1, b2, b3, bOff + kc * 32);
            MMA16816(d0, af[kc], b0, b1);
            MMA16816(d1, af[kc], b2, b3);
        }

        uint32_t ph[4];
        LDSM4(ph[0], ph[1], ph[2], ph[3], eAddr + ncp * 32);

        #pragma unroll
        for (int m = 0; m < 4; m++) {
            __nv_bfloat162 h = *(__nv_bfloat162*)&ph[m];
            float px = __low2float(h);
            float py = __high2float(h);
            const float* dd = (m & 2) ? d1 : d0;
            if (m & 1) {
                v1 = fmaf(dd[2], px, v1);
                v1 = fmaf(dd[3], py, v1);
            } else {
                v0 = fmaf(dd[0], px, v0);
                v0 = fmaf(dd[1], py, v0);
            }
        }
    }

    v0 += __shfl_xor_sync(0xffffffffu, v0, 1);
    v0 += __shfl_xor_sync(0xffffffffu, v0, 2);
    v1 += __shfl_xor_sync(0xffffffffu, v1, 1);
    v1 += __shfl_xor_sync(0xffffffffu, v1, 2);

    if (t4 == 0) {
        const float ms = *(const float*)(dsm + OFF_MS);
        float* outp = out + (size_t)b * (SS - 1) + t0;
        int i0 = rb + g, i1 = rb + g + 8;
        if (i0 < nout) {
            float4 T0 = tbl[i0], T1 = tbl[i0 + 1];
            outp[i0] = v0 - T1.x * T0.y - T0.x * T1.z + T0.x * T1.x * ms;
        }
        if (i1 < nout) {
            float4 T0 = tbl[i1], T1 = tbl[i1 + 1];
            outp[i1] = v1 - T1.x * T0.y - T0.x * T1.z + T0.x * T1.x * ms;
        }
    }
}

extern "C" void kernel_launch(void* const* d_in, const int* in_sizes, int n_in,
                              void* d_out, int out_size)
{
    const float* logits = (const float*)d_in[0];
    const float* M      = (const float*)d_in[1];
    float* out          = (float*)d_out;

    cudaFuncSetAttribute(pk_kernel, cudaFuncAttributeMaxDynamicSharedMemorySize, SMEM_TOTAL);
    dim3 grid(SS / TILE, BB);
    pk_kernel<<<grid, THREADS, SMEM_TOTAL>>>(logits, M, out);
}

// round 13
// speedup vs baseline: 3.2756x; 1.0352x over previous
#include <cuda_runtime.h>
#include <cuda_fp16.h>
#include <cstdint>

#define BB 128
#define SS 4096
#define CC 64
#define TILE 128
#define NW 8
#define THREADS (NW * 32)

#define SA 72            // f16 stride: 144B rows -> conflict-free
#define SB 72
#define OFF_A  0         // [129][72] f16 logits          = 18576
#define OFF_B  18576     // [72][72]  f16: M^T, u, w, 0s  = 10368
#define OFF_U  28944     // 64 f32 row sums u = M@1
#define OFF_W  29200     // 64 f32 col sums w = M^T@1
#define OFF_T  29456     // f32[132]  lse per token
#define OFF_T2 29984     // f32x2[130] (du, dw) per token
#define OFF_MS 31024     // 1 f32 sum(M)
#define SMEM_TOTAL 31040

#define MMA16816(d,a,b0,b1)                                                   \
    asm volatile("mma.sync.aligned.m16n8k16.row.col.f32.f16.f16.f32 "         \
        "{%0,%1,%2,%3}, {%4,%5,%6,%7}, {%8,%9}, {%0,%1,%2,%3};"               \
        : "+f"((d)[0]), "+f"((d)[1]), "+f"((d)[2]), "+f"((d)[3])              \
        : "r"((a)[0]), "r"((a)[1]), "r"((a)[2]), "r"((a)[3]), "r"(b0), "r"(b1))

#define LDSM4(r0,r1,r2,r3,addr)                                               \
    asm volatile("ldmatrix.sync.aligned.m8n8.x4.shared.b16 {%0,%1,%2,%3}, [%4];" \
        : "=r"(r0), "=r"(r1), "=r"(r2), "=r"(r3) : "r"(addr))

#define LDSM2(r0,r1,addr)                                                     \
    asm volatile("ldmatrix.sync.aligned.m8n8.x2.shared.b16 {%0,%1}, [%2];"    \
        : "=r"(r0), "=r"(r1) : "r"(addr))

static __device__ __forceinline__ uint32_t smem_u32(const void* p) {
    uint32_t a;
    asm("{ .reg .u64 t; cvta.to.shared.u64 t, %1; cvt.u32.u64 %0, t; }" : "=r"(a) : "l"(p));
    return a;
}

// ---- packed f32x2 ops ----
__device__ __forceinline__ float2 ffma2(float2 a, float2 b, float2 c) {
    float2 d;
    asm("{ .reg .b64 ra, rb, rc, rd;\n\t"
        "mov.b64 ra, {%2, %3}; mov.b64 rb, {%4, %5}; mov.b64 rc, {%6, %7};\n\t"
        "fma.rn.f32x2 rd, ra, rb, rc;\n\t"
        "mov.b64 {%0, %1}, rd; }"
        : "=f"(d.x), "=f"(d.y)
        : "f"(a.x), "f"(a.y), "f"(b.x), "f"(b.y), "f"(c.x), "f"(c.y));
    return d;
}
__device__ __forceinline__ float2 fmul2(float2 a, float2 b) {
    float2 d;
    asm("{ .reg .b64 ra, rb, rd;\n\t"
        "mov.b64 ra, {%2, %3}; mov.b64 rb, {%4, %5};\n\t"
        "mul.rn.f32x2 rd, ra, rb;\n\t"
        "mov.b64 {%0, %1}, rd; }"
        : "=f"(d.x), "=f"(d.y)
        : "f"(a.x), "f"(a.y), "f"(b.x), "f"(b.y));
    return d;
}

// paired exp(x) on FMA/ALU pipes (no MUFU)
__device__ __forceinline__ float2 fast_exp2x(float2 x) {
    const float L2E   = 1.4426950408889634f;
    const float MAGIC = 12582912.0f;               // 1.5 * 2^23
    float2 y = fmul2(x, make_float2(L2E, L2E));
    float2 t = ffma2(y, make_float2(1.f, 1.f), make_float2(MAGIC, MAGIC));
    float2 n = ffma2(t, make_float2(1.f, 1.f), make_float2(-MAGIC, -MAGIC));
    float2 f = ffma2(n, make_float2(-1.f, -1.f), y);
    float2 p = make_float2(1.3333558146428443e-3f, 1.3333558146428443e-3f);
    p = ffma2(p, f, make_float2(9.6181291076284772e-3f, 9.6181291076284772e-3f));
    p = ffma2(p, f, make_float2(5.5504108664798463e-2f, 5.5504108664798463e-2f));
    p = ffma2(p, f, make_float2(2.4022650695910072e-1f, 2.4022650695910072e-1f));
    p = ffma2(p, f, make_float2(6.9314718055994531e-1f, 6.9314718055994531e-1f));
    p = ffma2(p, f, make_float2(1.0f, 1.0f));
    float2 sc;
    sc.x = __int_as_float((__float_as_int(t.x) - 0x4B400000 + 127) << 23);
    sc.y = __int_as_float((__float_as_int(t.y) - 0x4B400000 + 127) << 23);
    return fmul2(p, sc);
}

// softmax-sum + store for a group of 4 token rows (2 tokens per warp half)
__device__ __forceinline__ void proc_tokens(
    const float4* xv, int tbase, int half, int qi,
    __half* A, float* tbl)
{
    float s[4];
    #pragma unroll
    for (int j = 0; j < 4; j++) {
        float2 e0 = fast_exp2x(make_float2(xv[j].x, xv[j].y));
        float2 e1 = fast_exp2x(make_float2(xv[j].z, xv[j].w));
        s[j] = (e0.x + e0.y) + (e1.x + e1.y);
    }
    #pragma unroll
    for (int o = 8; o; o >>= 1) {
        #pragma unroll
        for (int j = 0; j < 4; j++)
            s[j] += __shfl_xor_sync(0xffffffffu, s[j], o);
    }
    #pragma unroll
    for (int j = 0; j < 4; j++) {
        int t = tbase + 2 * j + half;
        if (qi == 0) tbl[t] = __logf(s[j]);
        __half2 h01 = __floats2half2_rn(xv[j].x, xv[j].y);
        __half2 h23 = __floats2half2_rn(xv[j].z, xv[j].w);
        *(uint2*)&A[t * SA + 4 * qi] = make_uint2(*(uint32_t*)&h01, *(uint32_t*)&h23);
    }
}

__global__ __launch_bounds__(THREADS, 4) void pk_kernel(
    const float* __restrict__ logits,
    const float* __restrict__ M,
    float* __restrict__ out)
{
    extern __shared__ char dsm[];
    __half*  A    = (__half*)(dsm + OFF_A);
    __half*  Bm   = (__half*)(dsm + OFF_B);
    float*   su   = (float*)(dsm + OFF_U);
    float*   sw   = (float*)(dsm + OFF_W);
    float*   tbl  = (float*)(dsm + OFF_T);
    float2*  tbl2 = (float2*)(dsm + OFF_T2);
    const uint32_t sb = smem_u32(dsm);

    const int b    = blockIdx.y;
    const int t0   = blockIdx.x * TILE;
    const int tid  = threadIdx.x;
    const int w    = tid >> 5;
    const int lane = tid & 31;

    const int ntok = min(TILE + 1, SS - t0);
    const int nout = min(TILE, SS - 1 - t0);

    // ---- stage B rows 0..63 = M^T (f16); zero rows 66..71; u, w fp32 ----
    for (int idx = tid; idx < CC * CC; idx += THREADS) {
        int k = idx >> 6, n = idx & 63;
        Bm[n * SB + k] = __float2half(M[idx]);
    }
    for (int idx = tid; idx < 6 * 64; idx += THREADS) {
        int rr = 66 + (idx >> 6), k = idx & 63;
        Bm[rr * SB + k] = __float2half(0.f);
    }
    if (tid < 64) {
        const float4* r = (const float4*)(M + tid * CC);
        float s = 0.f;
        #pragma unroll
        for (int i = 0; i < 16; i++) { float4 v = r[i]; s += (v.x + v.y) + (v.z + v.w); }
        su[tid] = s;
    } else if (tid < 128) {
        int c = tid - 64;
        float s = 0.f;
        #pragma unroll 8
        for (int d = 0; d < 64; d++) s += M[d * CC + c];
        sw[c] = s;
    }
    __syncthreads();

    // rows 64 = u, 65 = w (f16); ms
    if (tid < 64) {
        Bm[64 * SB + tid] = __float2half(su[tid]);
        Bm[65 * SB + tid] = __float2half(sw[tid]);
    }
    if (tid == 0) {
        float s = 0.f;
        #pragma unroll
        for (int i = 0; i < 64; i++) s += su[i];
        *(float*)(dsm + OFF_MS) = s;
    }

    // ---- phase 1: only lse reduction; x stored raw as f16 ----
    const float4* lg4 = (const float4*)(logits + ((size_t)b * SS + t0) * CC);
    const int half = lane >> 4;
    const int qi   = lane & 15;

    float4 xA[4], xB[4];
    #pragma unroll
    for (int j = 0; j < 4; j++) xA[j] = lg4[(w * 8 + 2 * j + half) * 16 + qi];
    #pragma unroll
    for (int j = 0; j < 4; j++) xB[j] = lg4[(64 + w * 8 + 2 * j + half) * 16 + qi];
    const bool has_tail = (w == 0) && (ntok > TILE);
    float4 xC = make_float4(0.f, 0.f, 0.f, 0.f);
    if (has_tail) xC = lg4[TILE * 16 + qi];

    proc_tokens(xA, w * 8, half, qi, A, tbl);
    proc_tokens(xB, 64 + w * 8, half, qi, A, tbl);

    if (has_tail) {
        float2 e0 = fast_exp2x(make_float2(xC.x, xC.y));
        float2 e1 = fast_exp2x(make_float2(xC.z, xC.w));
        float sC = (e0.x + e0.y) + (e1.x + e1.y);
        const float4 wv = ((const float4*)sw)[qi];
        float dwC = fmaf(xC.x, wv.x, fmaf(xC.y, wv.y, fmaf(xC.z, wv.z, xC.w * wv.w)));
        #pragma unroll
        for (int o = 8; o; o >>= 1) {
            sC  += __shfl_xor_sync(0xffffffffu, sC, o);
            dwC += __shfl_xor_sync(0xffffffffu, dwC, o);
        }
        if (half == 0) {
            if (qi == 0) {
                tbl[TILE]  = __logf(sC);
                tbl2[TILE] = make_float2(0.f, dwC);
            }
            __half2 h01 = __floats2half2_rn(xC.x, xC.y);
            __half2 h23 = __floats2half2_rn(xC.z, xC.w);
            *(uint2*)&A[TILE * SA + 4 * qi] =
                make_uint2(*(uint32_t*)&h01, *(uint32_t*)&h23);
        }
    }
    __syncthreads();

    // ---- phase 2: warp w owns token rows [16w, 16w+16) ----
    const int g  = lane >> 2;
    const int t4 = lane & 3;
    const int rb = w * 16;
    const int q  = lane >> 3;
    const int r  = lane & 7;

    const uint32_t aAddr = sb + (uint32_t)(((rb + r + (q & 1) * 8) * SA + (q >> 1) * 8) * 2);
    const uint32_t bAddr = sb + OFF_B + (uint32_t)(((r + (q >> 1) * 8) * SB + (q & 1) * 8) * 2);
    const uint32_t eAddr = sb + (uint32_t)(((rb + 1 + r + (q & 1) * 8) * SA + (q >> 1) * 8) * 2);
    const uint32_t b2Addr = sb + OFF_B +
        (uint32_t)(((64 + (lane & 7)) * SB + ((lane >> 3) & 1) * 8) * 2);

    uint32_t af[4][4];
    #pragma unroll
    for (int kc = 0; kc < 4; kc++)
        LDSM4(af[kc][0], af[kc][1], af[kc][2], af[kc][3], aAddr + kc * 32);

    float v0 = 0.f, v1 = 0.f;

    #pragma unroll
    for (int ncp = 0; ncp < 4; ncp++) {
        float d0[4] = {0.f, 0.f, 0.f, 0.f};
        float d1[4] = {0.f, 0.f, 0.f, 0.f};
        const uint32_t bOff = bAddr + (uint32_t)(ncp * 16 * SB * 2);

        #pragma unroll
        for (int kc = 0; kc < 4; kc++) {
            uint32_t b0, b1, b2, b3;
            LDSM4(b0, b1, b2, b3, bOff + kc * 32);
            MMA16816(d0, af[kc], b0, b1);
            MMA16816(d1, af[kc], b2, b3);
        }

        uint32_t ph[4];
        LDSM4(ph[0], ph[1], ph[2], ph[3], eAddr + ncp * 32);

        #pragma unroll
        for (int m = 0; m < 4; m++) {
            __half2 h = *(__half2*)&ph[m];
            float px = __low2float(h);
            float py = __high2float(h);
            if (m & 1) {
                const float* dd = (m & 2) ? d1 : d0;
                v1 = fmaf(dd[2], px, v1);
                v1 = fmaf(dd[3], py, v1);
            } else {
                const float* dd = (m & 2) ? d1 : d0;
                v0 = fmaf(dd[0], px, v0);
                v0 = fmaf(dd[1], py, v0);
            }
        }
    }

    // extra n-chunk: cols 64 (u) and 65 (w) -> per-token du, dw
    {
        float d64[4] = {0.f, 0.f, 0.f, 0.f};
        #pragma unroll
        for (int kc = 0; kc < 4; kc++) {
            uint32_t bb0, bb1;
            LDSM2(bb0, bb1, b2Addr + kc * 32);
            MMA16816(d64, af[kc], bb0, bb1);
        }
        if (t4 == 0) {
            tbl2[rb + g]     = make_float2(d64[0], d64[1]);
            tbl2[rb + g + 8] = make_float2(d64[2], d64[3]);
        }
    }

    v0 += __shfl_xor_sync(0xffffffffu, v0, 1);
    v0 += __shfl_xor_sync(0xffffffffu, v0, 2);
    v1 += __shfl_xor_sync(0xffffffffu, v1, 1);
    v1 += __shfl_xor_sync(0xffffffffu, v1, 2);

    __syncthreads();

    if (t4 == 0) {
        const float ms = *(const float*)(dsm + OFF_MS);
        float* outp = out + (size_t)b * (SS - 1) + t0;
        int i0 = rb + g, i1 = rb + g + 8;
        if (i0 < nout) {
            float l0 = tbl[i0], l1 = tbl[i0 + 1];
            float du = tbl2[i0].x, dw = tbl2[i0 + 1].y;
            outp[i0] = v0 - l1 * du - l0 * dw + l0 * l1 * ms;
        }
        if (i1 < nout) {
            float l0 = tbl[i1], l1 = tbl[i1 + 1];
            float du = tbl2[i1].x, dw = tbl2[i1 + 1].y;
            outp[i1] = v1 - l1 * du - l0 * dw + l0 * l1 * ms;
        }
    }
}

extern "C" void kernel_launch(void* const* d_in, const int* in_sizes, int n_in,
                              void* d_out, int out_size)
{
    const float* logits = (const float*)d_in[0];
    const float* M      = (const float*)d_in[1];
    float* out          = (float*)d_out;

    cudaFuncSetAttribute(pk_kernel, cudaFuncAttributeMaxDynamicSharedMemorySize, SMEM_TOTAL);
    dim3 grid(SS / TILE, BB);
    pk_kernel<<<grid, THREADS, SMEM_TOTAL>>>(logits, M, out);
}

// round 14
// speedup vs baseline: 4.2602x; 1.3006x over previous
#include <cuda_runtime.h>
#include <cuda_fp16.h>
#include <cstdint>

#define BB 128
#define SS 4096
#define CC 64
#define TILE 128
#define NT 4                      // tiles per CTA
#define NW 8
#define THREADS (NW * 32)

#define SA 72
#define SB 72
#define OFF_X0 0                  // [129][64] f32 logits buf 0 = 33024
#define OFF_X1 33024              // buf 1
#define OFF_A  66048              // [129][72] f16            = 18576
#define OFF_B  84624              // [72][72]  f16 M^T,u,w,0  = 10368
#define OFF_U  94992
#define OFF_W  95248
#define OFF_T  95504              // f32[132] lse
#define OFF_T2 96032              // f32x2[130] (du, dw)
#define OFF_MS 97072
#define SMEM_TOTAL 97080

#define MMA16816(d,a,b0,b1)                                                   \
    asm volatile("mma.sync.aligned.m16n8k16.row.col.f32.f16.f16.f32 "         \
        "{%0,%1,%2,%3}, {%4,%5,%6,%7}, {%8,%9}, {%0,%1,%2,%3};"               \
        : "+f"((d)[0]), "+f"((d)[1]), "+f"((d)[2]), "+f"((d)[3])              \
        : "r"((a)[0]), "r"((a)[1]), "r"((a)[2]), "r"((a)[3]), "r"(b0), "r"(b1))

#define LDSM4(r0,r1,r2,r3,addr)                                               \
    asm volatile("ldmatrix.sync.aligned.m8n8.x4.shared.b16 {%0,%1,%2,%3}, [%4];" \
        : "=r"(r0), "=r"(r1), "=r"(r2), "=r"(r3) : "r"(addr))

#define LDSM2(r0,r1,addr)                                                     \
    asm volatile("ldmatrix.sync.aligned.m8n8.x2.shared.b16 {%0,%1}, [%2];"    \
        : "=r"(r0), "=r"(r1) : "r"(addr))

static __device__ __forceinline__ uint32_t smem_u32(const void* p) {
    uint32_t a;
    asm("{ .reg .u64 t; cvta.to.shared.u64 t, %1; cvt.u32.u64 %0, t; }" : "=r"(a) : "l"(p));
    return a;
}

__device__ __forceinline__ float2 ffma2(float2 a, float2 b, float2 c) {
    float2 d;
    asm("{ .reg .b64 ra, rb, rc, rd;\n\t"
        "mov.b64 ra, {%2, %3}; mov.b64 rb, {%4, %5}; mov.b64 rc, {%6, %7};\n\t"
        "fma.rn.f32x2 rd, ra, rb, rc;\n\t"
        "mov.b64 {%0, %1}, rd; }"
        : "=f"(d.x), "=f"(d.y)
        : "f"(a.x), "f"(a.y), "f"(b.x), "f"(b.y), "f"(c.x), "f"(c.y));
    return d;
}
__device__ __forceinline__ float2 fmul2(float2 a, float2 b) {
    float2 d;
    asm("{ .reg .b64 ra, rb, rd;\n\t"
        "mov.b64 ra, {%2, %3}; mov.b64 rb, {%4, %5};\n\t"
        "mul.rn.f32x2 rd, ra, rb;\n\t"
        "mov.b64 {%0, %1}, rd; }"
        : "=f"(d.x), "=f"(d.y)
        : "f"(a.x), "f"(a.y), "f"(b.x), "f"(b.y));
    return d;
}

// paired exp(x) on FMA/ALU pipes (no MUFU)
__device__ __forceinline__ float2 fast_exp2x(float2 x) {
    const float L2E   = 1.4426950408889634f;
    const float MAGIC = 12582912.0f;
    float2 y = fmul2(x, make_float2(L2E, L2E));
    float2 t = ffma2(y, make_float2(1.f, 1.f), make_float2(MAGIC, MAGIC));
    float2 n = ffma2(t, make_float2(1.f, 1.f), make_float2(-MAGIC, -MAGIC));
    float2 f = ffma2(n, make_float2(-1.f, -1.f), y);
    float2 p = make_float2(1.3333558146428443e-3f, 1.3333558146428443e-3f);
    p = ffma2(p, f, make_float2(9.6181291076284772e-3f, 9.6181291076284772e-3f));
    p = ffma2(p, f, make_float2(5.5504108664798463e-2f, 5.5504108664798463e-2f));
    p = ffma2(p, f, make_float2(2.4022650695910072e-1f, 2.4022650695910072e-1f));
    p = ffma2(p, f, make_float2(6.9314718055994531e-1f, 6.9314718055994531e-1f));
    p = ffma2(p, f, make_float2(1.0f, 1.0f));
    float2 sc;
    sc.x = __int_as_float((__float_as_int(t.x) - 0x4B400000 + 127) << 23);
    sc.y = __int_as_float((__float_as_int(t.y) - 0x4B400000 + 127) << 23);
    return fmul2(p, sc);
}

// softmax-sum + store for 4 token rows (2 tokens per warp half)
__device__ __forceinline__ void proc_tokens(
    const float4* xv, int tbase, int half, int qi,
    __half* A, float* tbl)
{
    float s[4];
    #pragma unroll
    for (int j = 0; j < 4; j++) {
        float2 e0 = fast_exp2x(make_float2(xv[j].x, xv[j].y));
        float2 e1 = fast_exp2x(make_float2(xv[j].z, xv[j].w));
        s[j] = (e0.x + e0.y) + (e1.x + e1.y);
    }
    #pragma unroll
    for (int o = 8; o; o >>= 1) {
        #pragma unroll
        for (int j = 0; j < 4; j++)
            s[j] += __shfl_xor_sync(0xffffffffu, s[j], o);
    }
    #pragma unroll
    for (int j = 0; j < 4; j++) {
        int t = tbase + 2 * j + half;
        if (qi == 0) tbl[t] = __logf(s[j]);
        __half2 h01 = __floats2half2_rn(xv[j].x, xv[j].y);
        __half2 h23 = __floats2half2_rn(xv[j].z, xv[j].w);
        *(uint2*)&A[t * SA + 4 * qi] = make_uint2(*(uint32_t*)&h01, *(uint32_t*)&h23);
    }
}

__global__ __launch_bounds__(THREADS, 2) void pk_kernel(
    const float* __restrict__ logits,
    const float* __restrict__ M,
    float* __restrict__ out)
{
    extern __shared__ char dsm[];
    __half*  A    = (__half*)(dsm + OFF_A);
    __half*  Bm   = (__half*)(dsm + OFF_B);
    float*   su   = (float*)(dsm + OFF_U);
    float*   sw   = (float*)(dsm + OFF_W);
    float*   tbl  = (float*)(dsm + OFF_T);
    float2*  tbl2 = (float2*)(dsm + OFF_T2);
    const uint32_t sb = smem_u32(dsm);

    const int b    = blockIdx.y;
    const int t0   = blockIdx.x * (TILE * NT);
    const int tid  = threadIdx.x;
    const int w    = tid >> 5;
    const int lane = tid & 31;

    const float4* lgbase = (const float4*)(logits + (size_t)b * SS * CC);

    // ---- prefetch tile 0 ----
    {
        int g0 = t0;
        int n4 = min(TILE + 1, SS - g0) * 16;
        const float4* src = lgbase + g0 * 16;
        #pragma unroll 4
        for (int i = tid; i < n4; i += THREADS)
            asm volatile("cp.async.cg.shared.global [%0], [%1], 16;"
                         :: "r"(sb + OFF_X0 + i * 16), "l"(src + i) : "memory");
        asm volatile("cp.async.commit_group;" ::: "memory");
    }

    // ---- stage B rows 0..63 = M^T (f16); zero rows 66..71; u, w ----
    for (int idx = tid; idx < CC * CC; idx += THREADS) {
        int k = idx >> 6, n = idx & 63;
        Bm[n * SB + k] = __float2half(M[idx]);
    }
    for (int idx = tid; idx < 6 * 64; idx += THREADS) {
        int rr = 66 + (idx >> 6), k = idx & 63;
        Bm[rr * SB + k] = __float2half(0.f);
    }
    if (tid < 64) {
        const float4* r = (const float4*)(M + tid * CC);
        float s = 0.f;
        #pragma unroll
        for (int i = 0; i < 16; i++) { float4 v = r[i]; s += (v.x + v.y) + (v.z + v.w); }
        su[tid] = s;
    } else if (tid < 128) {
        int c = tid - 64;
        float s = 0.f;
        #pragma unroll 8
        for (int d = 0; d < 64; d++) s += M[d * CC + c];
        sw[c] = s;
    }
    __syncthreads();
    if (tid < 64) {
        Bm[64 * SB + tid] = __float2half(su[tid]);
        Bm[65 * SB + tid] = __float2half(sw[tid]);
    }
    if (tid == 0) {
        float s = 0.f;
        #pragma unroll
        for (int i = 0; i < 64; i++) s += su[i];
        *(float*)(dsm + OFF_MS) = s;
    }

    // phase-2 lane-invariant addresses (A/B layouts fixed across iterations)
    const int half = lane >> 4;
    const int qi   = lane & 15;
    const int g    = lane >> 2;
    const int t4   = lane & 3;
    const int rb   = w * 16;
    const int q    = lane >> 3;
    const int r    = lane & 7;
    const uint32_t aAddr = sb + OFF_A + (uint32_t)(((rb + r + (q & 1) * 8) * SA + (q >> 1) * 8) * 2);
    const uint32_t bAddr = sb + OFF_B + (uint32_t)(((r + (q >> 1) * 8) * SB + (q & 1) * 8) * 2);
    const uint32_t eAddr = sb + OFF_A + (uint32_t)(((rb + 1 + r + (q & 1) * 8) * SA + (q >> 1) * 8) * 2);
    const uint32_t b2Addr = sb + OFF_B +
        (uint32_t)(((64 + (lane & 7)) * SB + ((lane >> 3) & 1) * 8) * 2);

    for (int it = 0; it < NT; it++) {
        const int g0 = t0 + it * TILE;
        const int ntok = min(TILE + 1, SS - g0);
        const int nout = min(TILE, SS - 1 - g0);

        // prefetch next tile, then wait for current
        if (it + 1 < NT) {
            int g1 = g0 + TILE;
            int n4 = min(TILE + 1, SS - g1) * 16;
            const float4* src = lgbase + g1 * 16;
            uint32_t dst = sb + ((it + 1) & 1 ? OFF_X1 : OFF_X0);
            #pragma unroll 4
            for (int i = tid; i < n4; i += THREADS)
                asm volatile("cp.async.cg.shared.global [%0], [%1], 16;"
                             :: "r"(dst + i * 16), "l"(src + i) : "memory");
            asm volatile("cp.async.commit_group;" ::: "memory");
            asm volatile("cp.async.wait_group 1;" ::: "memory");
        } else {
            asm volatile("cp.async.wait_group 0;" ::: "memory");
        }
        __syncthreads();   // x buffer ready; previous phase-2 reads of A done

        const float4* xs = (const float4*)(dsm + (it & 1 ? OFF_X1 : OFF_X0));

        // ---- phase 1: lse + A (f16) from smem x ----
        float4 xA[4], xB[4];
        #pragma unroll
        for (int j = 0; j < 4; j++) xA[j] = xs[(w * 8 + 2 * j + half) * 16 + qi];
        #pragma unroll
        for (int j = 0; j < 4; j++) xB[j] = xs[(64 + w * 8 + 2 * j + half) * 16 + qi];
        const bool has_tail = (w == 0) && (ntok > TILE);
        float4 xC = make_float4(0.f, 0.f, 0.f, 0.f);
        if (has_tail) xC = xs[TILE * 16 + qi];

        proc_tokens(xA, w * 8, half, qi, A, tbl);
        proc_tokens(xB, 64 + w * 8, half, qi, A, tbl);

        if (has_tail) {
            float2 e0 = fast_exp2x(make_float2(xC.x, xC.y));
            float2 e1 = fast_exp2x(make_float2(xC.z, xC.w));
            float sC = (e0.x + e0.y) + (e1.x + e1.y);
            const float4 wv = ((const float4*)sw)[qi];
            float dwC = fmaf(xC.x, wv.x, fmaf(xC.y, wv.y, fmaf(xC.z, wv.z, xC.w * wv.w)));
            #pragma unroll
            for (int o = 8; o; o >>= 1) {
                sC  += __shfl_xor_sync(0xffffffffu, sC, o);
                dwC += __shfl_xor_sync(0xffffffffu, dwC, o);
            }
            if (half == 0) {
                if (qi == 0) {
                    tbl[TILE]  = __logf(sC);
                    tbl2[TILE] = make_float2(0.f, dwC);
                }
                __half2 h01 = __floats2half2_rn(xC.x, xC.y);
                __half2 h23 = __floats2half2_rn(xC.z, xC.w);
                *(uint2*)&A[TILE * SA + 4 * qi] =
                    make_uint2(*(uint32_t*)&h01, *(uint32_t*)&h23);
            }
        }
        __syncthreads();

        // ---- phase 2 ----
        uint32_t af[4][4];
        #pragma unroll
        for (int kc = 0; kc < 4; kc++)
            LDSM4(af[kc][0], af[kc][1], af[kc][2], af[kc][3], aAddr + kc * 32);

        float v0 = 0.f, v1 = 0.f;

        #pragma unroll
        for (int ncp = 0; ncp < 4; ncp++) {
            float d0[4] = {0.f, 0.f, 0.f, 0.f};
            float d1[4] = {0.f, 0.f, 0.f, 0.f};
            const uint32_t bOff = bAddr + (uint32_t)(ncp * 16 * SB * 2);

            #pragma unroll
            for (int kc = 0; kc < 4; kc++) {
                uint32_t b0, b1, b2, b3;
                LDSM4(b0, b1, b2, b3, bOff + kc * 32);
                MMA16816(d0, af[kc], b0, b1);
                MMA16816(d1, af[kc], b2, b3);
            }

            uint32_t ph[4];
            LDSM4(ph[0], ph[1], ph[2], ph[3], eAddr + ncp * 32);

            #pragma unroll
            for (int m = 0; m < 4; m++) {
                __half2 h = *(__half2*)&ph[m];
                float px = __low2float(h);
                float py = __high2float(h);
                const float* dd = (m & 2) ? d1 : d0;
                if (m & 1) {
                    v1 = fmaf(dd[2], px, v1);
                    v1 = fmaf(dd[3], py, v1);
                } else {
                    v0 = fmaf(dd[0], px, v0);
                    v0 = fmaf(dd[1], py, v0);
                }
            }
        }

        {   // extra n-chunk: cols 64 (u), 65 (w)
            float d64[4] = {0.f, 0.f, 0.f, 0.f};
            #pragma unroll
            for (int kc = 0; kc < 4; kc++) {
                uint32_t bb0, bb1;
                LDSM2(bb0, bb1, b2Addr + kc * 32);
                MMA16816(d64, af[kc], bb0, bb1);
            }
            if (t4 == 0) {
                tbl2[rb + g]     = make_float2(d64[0], d64[1]);
                tbl2[rb + g + 8] = make_float2(d64[2], d64[3]);
            }
        }

        v0 += __shfl_xor_sync(0xffffffffu, v0, 1);
        v0 += __shfl_xor_sync(0xffffffffu, v0, 2);
        v1 += __shfl_xor_sync(0xffffffffu, v1, 1);
        v1 += __shfl_xor_sync(0xffffffffu, v1, 2);

        __syncthreads();

        if (t4 == 0) {
            const float ms = *(const float*)(dsm + OFF_MS);
            float* outp = out + (size_t)b * (SS - 1) + g0;
            int i0 = rb + g, i1 = rb + g + 8;
            if (i0 < nout) {
                float l0 = tbl[i0], l1 = tbl[i0 + 1];
                outp[i0] = v0 - l1 * tbl2[i0].x - l0 * tbl2[i0 + 1].y + l0 * l1 * ms;
            }
            if (i1 < nout) {
                float l0 = tbl[i1], l1 = tbl[i1 + 1];
                outp[i1] = v1 - l1 * tbl2[i1].x - l0 * tbl2[i1 + 1].y + l0 * l1 * ms;
            }
        }
    }
}

extern "C" void kernel_launch(void* const* d_in, const int* in_sizes, int n_in,
                              void* d_out, int out_size)
{
    const float* logits = (const float*)d_in[0];
    const float* M      = (const float*)d_in[1];
    float* out          = (float*)d_out;

    cudaFuncSetAttribute(pk_kernel, cudaFuncAttributeMaxDynamicSharedMemorySize, SMEM_TOTAL);
    dim3 grid(SS / (TILE * NT), BB);
    pk_kernel<<<grid, THREADS, SMEM_TOTAL>>>(logits, M, out);
}

// round 15
// speedup vs baseline: 4.8323x; 1.1343x over previous
#include <cuda_runtime.h>
#include <cuda_fp16.h>
#include <cstdint>

#define BB 128
#define SS 4096
#define CC 64
#define TILE 128
#define NW 8
#define THREADS (NW * 32)
#define TILES_PER_B (SS / TILE)          // 32
#define TT (BB * TILES_PER_B)            // 4096 tiles total

#define SA 72
#define SB 72
#define OFF_X0 0                  // [129][64] f32 logits buf 0 = 33024
#define OFF_X1 33024              // buf 1
#define OFF_A  66048              // [129][72] f16            = 18576
#define OFF_B  84624              // [72][72]  f16 M^T,u,w,0  = 10368
#define OFF_U  94992
#define OFF_W  95248
#define OFF_T  95504              // f32[132] lse
#define OFF_T2 96032              // f32x2[130] (du, dw)
#define OFF_MS 97072
#define SMEM_TOTAL 97080

#define MMA16816(d,a,b0,b1)                                                   \
    asm volatile("mma.sync.aligned.m16n8k16.row.col.f32.f16.f16.f32 "         \
        "{%0,%1,%2,%3}, {%4,%5,%6,%7}, {%8,%9}, {%0,%1,%2,%3};"               \
        : "+f"((d)[0]), "+f"((d)[1]), "+f"((d)[2]), "+f"((d)[3])              \
        : "r"((a)[0]), "r"((a)[1]), "r"((a)[2]), "r"((a)[3]), "r"(b0), "r"(b1))

#define LDSM4(r0,r1,r2,r3,addr)                                               \
    asm volatile("ldmatrix.sync.aligned.m8n8.x4.shared.b16 {%0,%1,%2,%3}, [%4];" \
        : "=r"(r0), "=r"(r1), "=r"(r2), "=r"(r3) : "r"(addr))

#define LDSM2(r0,r1,addr)                                                     \
    asm volatile("ldmatrix.sync.aligned.m8n8.x2.shared.b16 {%0,%1}, [%2];"    \
        : "=r"(r0), "=r"(r1) : "r"(addr))

static __device__ __forceinline__ uint32_t smem_u32(const void* p) {
    uint32_t a;
    asm("{ .reg .u64 t; cvta.to.shared.u64 t, %1; cvt.u32.u64 %0, t; }" : "=r"(a) : "l"(p));
    return a;
}

__device__ __forceinline__ float2 ffma2(float2 a, float2 b, float2 c) {
    float2 d;
    asm("{ .reg .b64 ra, rb, rc, rd;\n\t"
        "mov.b64 ra, {%2, %3}; mov.b64 rb, {%4, %5}; mov.b64 rc, {%6, %7};\n\t"
        "fma.rn.f32x2 rd, ra, rb, rc;\n\t"
        "mov.b64 {%0, %1}, rd; }"
        : "=f"(d.x), "=f"(d.y)
        : "f"(a.x), "f"(a.y), "f"(b.x), "f"(b.y), "f"(c.x), "f"(c.y));
    return d;
}
__device__ __forceinline__ float2 fmul2(float2 a, float2 b) {
    float2 d;
    asm("{ .reg .b64 ra, rb, rd;\n\t"
        "mov.b64 ra, {%2, %3}; mov.b64 rb, {%4, %5};\n\t"
        "mul.rn.f32x2 rd, ra, rb;\n\t"
        "mov.b64 {%0, %1}, rd; }"
        : "=f"(d.x), "=f"(d.y)
        : "f"(a.x), "f"(a.y), "f"(b.x), "f"(b.y));
    return d;
}

// paired exp(x) on FMA/ALU pipes (no MUFU)
__device__ __forceinline__ float2 fast_exp2x(float2 x) {
    const float L2E   = 1.4426950408889634f;
    const float MAGIC = 12582912.0f;
    float2 y = fmul2(x, make_float2(L2E, L2E));
    float2 t = ffma2(y, make_float2(1.f, 1.f), make_float2(MAGIC, MAGIC));
    float2 n = ffma2(t, make_float2(1.f, 1.f), make_float2(-MAGIC, -MAGIC));
    float2 f = ffma2(n, make_float2(-1.f, -1.f), y);
    float2 p = make_float2(1.3333558146428443e-3f, 1.3333558146428443e-3f);
    p = ffma2(p, f, make_float2(9.6181291076284772e-3f, 9.6181291076284772e-3f));
    p = ffma2(p, f, make_float2(5.5504108664798463e-2f, 5.5504108664798463e-2f));
    p = ffma2(p, f, make_float2(2.4022650695910072e-1f, 2.4022650695910072e-1f));
    p = ffma2(p, f, make_float2(6.9314718055994531e-1f, 6.9314718055994531e-1f));
    p = ffma2(p, f, make_float2(1.0f, 1.0f));
    float2 sc;
    sc.x = __int_as_float((__float_as_int(t.x) - 0x4B400000 + 127) << 23);
    sc.y = __int_as_float((__float_as_int(t.y) - 0x4B400000 + 127) << 23);
    return fmul2(p, sc);
}

// softmax-sum + store for 4 token rows (2 tokens per warp half)
__device__ __forceinline__ void proc_tokens(
    const float4* xv, int tbase, int half, int qi,
    __half* A, float* tbl)
{
    float s[4];
    #pragma unroll
    for (int j = 0; j < 4; j++) {
        float2 e0 = fast_exp2x(make_float2(xv[j].x, xv[j].y));
        float2 e1 = fast_exp2x(make_float2(xv[j].z, xv[j].w));
        s[j] = (e0.x + e0.y) + (e1.x + e1.y);
    }
    #pragma unroll
    for (int o = 8; o; o >>= 1) {
        #pragma unroll
        for (int j = 0; j < 4; j++)
            s[j] += __shfl_xor_sync(0xffffffffu, s[j], o);
    }
    #pragma unroll
    for (int j = 0; j < 4; j++) {
        int t = tbase + 2 * j + half;
        if (qi == 0) tbl[t] = __logf(s[j]);
        __half2 h01 = __floats2half2_rn(xv[j].x, xv[j].y);
        __half2 h23 = __floats2half2_rn(xv[j].z, xv[j].w);
        *(uint2*)&A[t * SA + 4 * qi] = make_uint2(*(uint32_t*)&h01, *(uint32_t*)&h23);
    }
}

// issue cp.async for one tile's logits into X buffer
__device__ __forceinline__ void prefetch_tile(
    const float* logits, int tile, uint32_t dst, int tid)
{
    int b  = tile >> 5;                       // / TILES_PER_B
    int t0 = (tile & 31) * TILE;
    int n4 = min(TILE + 1, SS - t0) * 16;
    const float4* src = (const float4*)(logits + ((size_t)b * SS + t0) * CC);
    #pragma unroll 4
    for (int i = tid; i < n4; i += THREADS)
        asm volatile("cp.async.cg.shared.global [%0], [%1], 16;"
                     :: "r"(dst + i * 16), "l"(src + i) : "memory");
    asm volatile("cp.async.commit_group;" ::: "memory");
}

__global__ __launch_bounds__(THREADS, 2) void pk_kernel(
    const float* __restrict__ logits,
    const float* __restrict__ M,
    float* __restrict__ out)
{
    extern __shared__ char dsm[];
    __half*  A    = (__half*)(dsm + OFF_A);
    __half*  Bm   = (__half*)(dsm + OFF_B);
    float*   su   = (float*)(dsm + OFF_U);
    float*   sw   = (float*)(dsm + OFF_W);
    float*   tbl  = (float*)(dsm + OFF_T);
    float2*  tbl2 = (float2*)(dsm + OFF_T2);
    const uint32_t sb = smem_u32(dsm);

    const int tid  = threadIdx.x;
    const int w    = tid >> 5;
    const int lane = tid & 31;
    const int G    = gridDim.x;

    int tile = blockIdx.x;
    if (tile < TT) prefetch_tile(logits, tile, sb + OFF_X0, tid);

    // ---- stage B rows 0..63 = M^T (f16); zero rows 66..71; u, w ----
    for (int idx = tid; idx < CC * CC; idx += THREADS) {
        int k = idx >> 6, n = idx & 63;
        Bm[n * SB + k] = __float2half(M[idx]);
    }
    for (int idx = tid; idx < 6 * 64; idx += THREADS) {
        int rr = 66 + (idx >> 6), k = idx & 63;
        Bm[rr * SB + k] = __float2half(0.f);
    }
    if (tid < 64) {
        const float4* rr = (const float4*)(M + tid * CC);
        float s = 0.f;
        #pragma unroll
        for (int i = 0; i < 16; i++) { float4 v = rr[i]; s += (v.x + v.y) + (v.z + v.w); }
        su[tid] = s;
    } else if (tid < 128) {
        int c = tid - 64;
        float s = 0.f;
        #pragma unroll 8
        for (int d = 0; d < 64; d++) s += M[d * CC + c];
        sw[c] = s;
    }
    __syncthreads();
    if (tid < 64) {
        Bm[64 * SB + tid] = __float2half(su[tid]);
        Bm[65 * SB + tid] = __float2half(sw[tid]);
    }
    if (tid == 0) {
        float s = 0.f;
        #pragma unroll
        for (int i = 0; i < 64; i++) s += su[i];
        *(float*)(dsm + OFF_MS) = s;
    }

    // lane-invariant addresses
    const int half = lane >> 4;
    const int qi   = lane & 15;
    const int g    = lane >> 2;
    const int t4   = lane & 3;
    const int rb   = w * 16;
    const int q    = lane >> 3;
    const int r    = lane & 7;
    const uint32_t aAddr = sb + OFF_A + (uint32_t)(((rb + r + (q & 1) * 8) * SA + (q >> 1) * 8) * 2);
    const uint32_t bAddr = sb + OFF_B + (uint32_t)(((r + (q >> 1) * 8) * SB + (q & 1) * 8) * 2);
    const uint32_t eAddr = sb + OFF_A + (uint32_t)(((rb + 1 + r + (q & 1) * 8) * SA + (q >> 1) * 8) * 2);
    const uint32_t b2Addr = sb + OFF_B +
        (uint32_t)(((64 + (lane & 7)) * SB + ((lane >> 3) & 1) * 8) * 2);

    int buf = 0;
    for (; tile < TT; tile += G, buf ^= 1) {
        const int b  = tile >> 5;
        const int t0 = (tile & 31) * TILE;
        const int ntok = min(TILE + 1, SS - t0);
        const int nout = min(TILE, SS - 1 - t0);

        // prefetch this CTA's next tile into the other buffer, wait for current
        const int nxt = tile + G;
        if (nxt < TT) {
            prefetch_tile(logits, nxt, sb + (buf ? OFF_X0 : OFF_X1), tid);
            asm volatile("cp.async.wait_group 1;" ::: "memory");
        } else {
            asm volatile("cp.async.wait_group 0;" ::: "memory");
        }
        __syncthreads();   // x ready; previous iteration's A reads done

        const float4* xs = (const float4*)(dsm + (buf ? OFF_X1 : OFF_X0));

        // ---- phase 1 ----
        float4 xA[4], xB[4];
        #pragma unroll
        for (int j = 0; j < 4; j++) xA[j] = xs[(w * 8 + 2 * j + half) * 16 + qi];
        #pragma unroll
        for (int j = 0; j < 4; j++) xB[j] = xs[(64 + w * 8 + 2 * j + half) * 16 + qi];
        const bool has_tail = (w == 0) && (ntok > TILE);
        float4 xC = make_float4(0.f, 0.f, 0.f, 0.f);
        if (has_tail) xC = xs[TILE * 16 + qi];

        proc_tokens(xA, w * 8, half, qi, A, tbl);
        proc_tokens(xB, 64 + w * 8, half, qi, A, tbl);

        if (has_tail) {
            float2 e0 = fast_exp2x(make_float2(xC.x, xC.y));
            float2 e1 = fast_exp2x(make_float2(xC.z, xC.w));
            float sC = (e0.x + e0.y) + (e1.x + e1.y);
            const float4 wv = ((const float4*)sw)[qi];
            float dwC = fmaf(xC.x, wv.x, fmaf(xC.y, wv.y, fmaf(xC.z, wv.z, xC.w * wv.w)));
            #pragma unroll
            for (int o = 8; o; o >>= 1) {
                sC  += __shfl_xor_sync(0xffffffffu, sC, o);
                dwC += __shfl_xor_sync(0xffffffffu, dwC, o);
            }
            if (half == 0) {
                if (qi == 0) {
                    tbl[TILE]  = __logf(sC);
                    tbl2[TILE] = make_float2(0.f, dwC);
                }
                __half2 h01 = __floats2half2_rn(xC.x, xC.y);
                __half2 h23 = __floats2half2_rn(xC.z, xC.w);
                *(uint2*)&A[TILE * SA + 4 * qi] =
                    make_uint2(*(uint32_t*)&h01, *(uint32_t*)&h23);
            }
        }
        __syncthreads();

        // ---- phase 2 ----
        uint32_t af[4][4];
        #pragma unroll
        for (int kc = 0; kc < 4; kc++)
            LDSM4(af[kc][0], af[kc][1], af[kc][2], af[kc][3], aAddr + kc * 32);

        float v0 = 0.f, v1 = 0.f;

        #pragma unroll
        for (int ncp = 0; ncp < 4; ncp++) {
            float d0[4] = {0.f, 0.f, 0.f, 0.f};
            float d1[4] = {0.f, 0.f, 0.f, 0.f};
            const uint32_t bOff = bAddr + (uint32_t)(ncp * 16 * SB * 2);

            #pragma unroll
            for (int kc = 0; kc < 4; kc++) {
                uint32_t b0, b1, b2, b3;
                LDSM4(b0, b1, b2, b3, bOff + kc * 32);
                MMA16816(d0, af[kc], b0, b1);
                MMA16816(d1, af[kc], b2, b3);
            }

            uint32_t ph[4];
            LDSM4(ph[0], ph[1], ph[2], ph[3], eAddr + ncp * 32);

            #pragma unroll
            for (int m = 0; m < 4; m++) {
                __half2 h = *(__half2*)&ph[m];
                float px = __low2float(h);
                float py = __high2float(h);
                const float* dd = (m & 2) ? d1 : d0;
                if (m & 1) {
                    v1 = fmaf(dd[2], px, v1);
                    v1 = fmaf(dd[3], py, v1);
                } else {
                    v0 = fmaf(dd[0], px, v0);
                    v0 = fmaf(dd[1], py, v0);
                }
            }
        }

        {   // extra n-chunk: cols 64 (u), 65 (w)
            float d64[4] = {0.f, 0.f, 0.f, 0.f};
            #pragma unroll
            for (int kc = 0; kc < 4; kc++) {
                uint32_t bb0, bb1;
                LDSM2(bb0, bb1, b2Addr + kc * 32);
                MMA16816(d64, af[kc], bb0, bb1);
            }
            if (t4 == 0) {
                tbl2[rb + g]     = make_float2(d64[0], d64[1]);
                tbl2[rb + g + 8] = make_float2(d64[2], d64[3]);
            }
        }

        v0 += __shfl_xor_sync(0xffffffffu, v0, 1);
        v0 += __shfl_xor_sync(0xffffffffu, v0, 2);
        v1 += __shfl_xor_sync(0xffffffffu, v1, 1);
        v1 += __shfl_xor_sync(0xffffffffu, v1, 2);

        __syncthreads();

        if (t4 == 0) {
            const float ms = *(const float*)(dsm + OFF_MS);
            float* outp = out + (size_t)b * (SS - 1) + t0;
            int i0 = rb + g, i1 = rb + g + 8;
            if (i0 < nout) {
                float l0 = tbl[i0], l1 = tbl[i0 + 1];
                outp[i0] = v0 - l1 * tbl2[i0].x - l0 * tbl2[i0 + 1].y + l0 * l1 * ms;
            }
            if (i1 < nout) {
                float l0 = tbl[i1], l1 = tbl[i1 + 1];
                outp[i1] = v1 - l1 * tbl2[i1].x - l0 * tbl2[i1 + 1].y + l0 * l1 * ms;
            }
        }
    }
}

extern "C" void kernel_launch(void* const* d_in, const int* in_sizes, int n_in,
                              void* d_out, int out_size)
{
    const float* logits = (const float*)d_in[0];
    const float* M      = (const float*)d_in[1];
    float* out          = (float*)d_out;

    int sms = 148;
    cudaDeviceGetAttribute(&sms, cudaDevAttrMultiProcessorCount, 0);
    int grid = 2 * sms;
    if (grid > TT) grid = TT;

    cudaFuncSetAttribute(pk_kernel, cudaFuncAttributeMaxDynamicSharedMemorySize, SMEM_TOTAL);
    pk_kernel<<<grid, THREADS, SMEM_TOTAL>>>(logits, M, out);
}